// round 5
// baseline (speedup 1.0000x reference)
#include <cuda_runtime.h>
#include <math_constants.h>
#include <cstdint>
#include <cstddef>

static constexpr int Vv = 16000, Cc = 4096, Hh = 256, SPW = 32, Nn = 32, Tt = 128, Tm1 = 127;

// ---------------- scratch layout ----------------
constexpr size_t SZ_MAT   = (size_t)Cc * Hh;                  // 1,048,576
constexpr size_t OFF_RS   = 0;
constexpr size_t OFF_RP   = OFF_RS   + SZ_MAT;
constexpr size_t OFF_TRANS= OFF_RP   + SZ_MAT;                // 4096x4096
constexpr size_t OFF_TLSE = OFF_TRANS+ (size_t)Cc * Cc;
constexpr size_t OFF_SLOG = OFF_TLSE + Cc;
constexpr size_t OFF_SLSE = OFF_SLOG + Cc;
constexpr size_t OFF_EWT  = OFF_SLSE + 32;                    // V x H
constexpr size_t OFF_L    = OFF_EWT  + (size_t)Vv * Hh;       // V x SPW
constexpr size_t OFF_RSUM = OFF_L    + (size_t)Vv * SPW;
constexpr size_t OFF_STLSE= OFF_RSUM + Cc;
constexpr size_t OFF_PHI  = OFF_STLSE+ Cc;                    // Tm1*N*32*32
constexpr size_t OFF_AP   = OFF_PHI  + (size_t)Tm1 * Nn * SPW * SPW;
constexpr size_t OFF_BN   = OFF_AP   + (size_t)Tm1 * Nn * SPW;
constexpr size_t OFF_LOGZ = OFF_BN   + (size_t)Tm1 * Nn * SPW;
constexpr size_t OFF_PART = OFF_LOGZ + 64;                    // 4096 x 128 x (m,s)
constexpr size_t SCRATCH_TOTAL = OFF_PART + (size_t)Cc * 128 * 2;

__device__ float g_scr[SCRATCH_TOTAL];
__device__ int   g_rowmax[Cc];

// tf32 hi/lo split buffers (u32 elements)
constexpr size_t WSZ = (size_t)Hh * Hh;                       // 65536
constexpr size_t UAH = 0, UAL = SZ_MAT;                       // RST split (A of trans GEMM)
constexpr size_t UBH = 2 * SZ_MAT, UBL = 3 * SZ_MAT;          // nsp split
constexpr size_t UEMB = 4 * SZ_MAT;                           // 3 x (hi,lo) embeddings
constexpr size_t UHB  = 10 * SZ_MAT;                          // 3 x (hi,lo) H outputs
constexpr size_t UWB  = 16 * SZ_MAT;                          // 6 x (hi,lo) weights
__device__ uint32_t g_u[16 * SZ_MAT + 12 * WSZ];

// ---------------- helpers ----------------
__device__ __forceinline__ int ford(float f) {
    int i = __float_as_int(f);
    return i >= 0 ? i : (i ^ 0x7fffffff);
}
__device__ __forceinline__ float deord(int i) {
    return __int_as_float(i >= 0 ? i : (i ^ 0x7fffffff));
}
__device__ __forceinline__ void lse_acc(float& m, float& s, float v) {
    if (v > m) { s = s * __expf(m - v) + 1.f; m = v; }
    else       { s += __expf(v - m); }
}
__device__ __forceinline__ void lse_merge(float& m, float& s, float m2, float s2) {
    if (m2 > m) { s = s * __expf(m - m2) + s2; m = m2; }
    else        { s += s2 * __expf(m2 - m); }
}
__device__ __forceinline__ float warp_sum(float v) {
#pragma unroll
    for (int o = 16; o > 0; o >>= 1) v += __shfl_xor_sync(0xffffffffu, v, o);
    return v;
}
__device__ __forceinline__ float warp_max(float v) {
#pragma unroll
    for (int o = 16; o > 0; o >>= 1) v = fmaxf(v, __shfl_xor_sync(0xffffffffu, v, o));
    return v;
}

// ---------------- tf32 utils ----------------
__device__ __forceinline__ uint32_t f2tf(float x) {
    uint32_t r;
    asm("cvt.rna.tf32.f32 %0, %1;" : "=r"(r) : "f"(x));
    return r;
}
__device__ __forceinline__ void tf_split(float x, uint32_t& hi, uint32_t& lo) {
    hi = f2tf(x);
    lo = f2tf(x - __uint_as_float(hi));
}
__device__ __forceinline__ void mma_tf32(float4& d, const uint32_t* a, const uint32_t* b) {
    asm volatile(
        "mma.sync.aligned.m16n8k8.row.col.f32.tf32.tf32.f32 "
        "{%0,%1,%2,%3}, {%4,%5,%6,%7}, {%8,%9}, {%0,%1,%2,%3};"
        : "+f"(d.x), "+f"(d.y), "+f"(d.z), "+f"(d.w)
        : "r"(a[0]), "r"(a[1]), "r"(a[2]), "r"(a[3]), "r"(b[0]), "r"(b[1]));
}
__device__ __forceinline__ void cpasync16(uint32_t dst, const void* src) {
    asm volatile("cp.async.cg.shared.global [%0], [%1], 16;" :: "r"(dst), "l"(src));
}
__device__ __forceinline__ void cp_commit() { asm volatile("cp.async.commit_group;"); }
template <int N> __device__ __forceinline__ void cp_wait() {
    asm volatile("cp.async.wait_group %0;" :: "n"(N));
}

// ---------------- presplit kernels ----------------
struct SP { const float* in; uint32_t* hi; uint32_t* lo; };
struct SP4 { SP p[4]; };
__global__ void presplit4_k(SP4 b) {
    const SP pp = b.p[blockIdx.z];
    int i = blockIdx.x * blockDim.x + threadIdx.x;
    float4 v = ((const float4*)pp.in)[i];
    uint4 h, l;
    tf_split(v.x, h.x, l.x); tf_split(v.y, h.y, l.y);
    tf_split(v.z, h.z, l.z); tf_split(v.w, h.w, l.w);
    ((uint4*)pp.hi)[i] = h; ((uint4*)pp.lo)[i] = l;
}

// transpose + split 256x256 weights: out[n][k] = w[k][n]
struct WP { const float* w; uint32_t* hi; uint32_t* lo; };
struct WP6 { WP p[6]; };
__global__ void wtsplit_k(WP6 b) {
    const WP pp = b.p[blockIdx.z];
    __shared__ float t[32][33];
    int bx = blockIdx.x * 32, by = blockIdx.y * 32;
    int x = threadIdx.x, y = threadIdx.y;
#pragma unroll
    for (int i = 0; i < 32; i += 8)
        t[y + i][x] = pp.w[(size_t)(by + y + i) * Hh + bx + x];
    __syncthreads();
#pragma unroll
    for (int i = 0; i < 32; i += 8) {
        float v = t[x][y + i];
        uint32_t h, l;
        tf_split(v, h, l);
        pp.hi[(size_t)(bx + y + i) * Hh + by + x] = h;
        pp.lo[(size_t)(bx + y + i) * Hh + by + x] = l;
    }
}

// ---------------- MLP GEMM: 128x64 tile pipelined pre-split (as round 4) -------
struct PP { const uint32_t *Ah, *Al, *Bh, *Bl; const float *bias, *R;
            float *C; uint32_t *Ch, *Cl; };
struct PP3 { PP p[3]; };

template <int EPI>
__global__ __launch_bounds__(256) void gemmp(PP3 bt, int N) {
    constexpr int K = 256, NIT = K / 8, BUF = 4608;
    __shared__ uint32_t smem[2 * BUF];
    const PP pp = bt.p[blockIdx.z];
    int tid = threadIdx.x, wid = tid >> 5, lane = tid & 31;
    int gid = lane >> 2, tg = lane & 3;
    int bm = blockIdx.y * 128, bn = blockIdx.x * 64;
    int warp_m = (wid & 3) * 32, warp_n = (wid >> 2) * 32;

    const uint32_t* gsrc[3]; uint32_t doff[3];
#pragma unroll
    for (int i = 0; i < 3; i++) {
        int ch = tid + i * 256;
        if (ch < 512) {
            int mat = ch >> 8, r = (ch >> 1) & 127, c4 = (ch & 1) * 4;
            gsrc[i] = (mat ? pp.Al : pp.Ah) + (size_t)(bm + r) * K + c4;
            doff[i] = mat * 1536 + r * 12 + c4;
        } else {
            int idx = ch - 512;
            int mat = idx >> 7, r = (idx >> 1) & 63, c4 = (idx & 1) * 4;
            gsrc[i] = (mat ? pp.Bl : pp.Bh) + (size_t)(bn + r) * K + c4;
            doff[i] = 3072 + mat * 768 + r * 12 + c4;
        }
    }
    uint32_t sbase = (uint32_t)__cvta_generic_to_shared(smem);

    float4 acc[2][4];
#pragma unroll
    for (int i = 0; i < 2; i++)
#pragma unroll
        for (int j = 0; j < 4; j++) acc[i][j] = make_float4(0.f, 0.f, 0.f, 0.f);

    {
#pragma unroll
        for (int i = 0; i < 3; i++) cpasync16(sbase + doff[i] * 4, gsrc[i]);
        cp_commit();
    }
    for (int it = 0; it < NIT; it++) {
        if (it + 1 < NIT) {
            uint32_t b = sbase + ((it + 1) & 1) * (BUF * 4);
#pragma unroll
            for (int i = 0; i < 3; i++) cpasync16(b + doff[i] * 4, gsrc[i] + (it + 1) * 8);
            cp_commit();
            cp_wait<1>();
        } else {
            cp_wait<0>();
        }
        __syncthreads();
        const uint32_t* buf = smem + (it & 1) * BUF;
        uint32_t ah[2][4], al[2][4], bh[4][2], bl[4][2];
#pragma unroll
        for (int mt = 0; mt < 2; mt++) {
            int rb = warp_m + mt * 16 + gid;
            ah[mt][0] = buf[rb * 12 + tg];           al[mt][0] = buf[1536 + rb * 12 + tg];
            ah[mt][1] = buf[(rb + 8) * 12 + tg];     al[mt][1] = buf[1536 + (rb + 8) * 12 + tg];
            ah[mt][2] = buf[rb * 12 + tg + 4];       al[mt][2] = buf[1536 + rb * 12 + tg + 4];
            ah[mt][3] = buf[(rb + 8) * 12 + tg + 4]; al[mt][3] = buf[1536 + (rb + 8) * 12 + tg + 4];
        }
#pragma unroll
        for (int nt = 0; nt < 4; nt++) {
            int cb = warp_n + nt * 8 + gid;
            bh[nt][0] = buf[3072 + cb * 12 + tg];     bl[nt][0] = buf[3840 + cb * 12 + tg];
            bh[nt][1] = buf[3072 + cb * 12 + tg + 4]; bl[nt][1] = buf[3840 + cb * 12 + tg + 4];
        }
#pragma unroll
        for (int mt = 0; mt < 2; mt++)
#pragma unroll
            for (int nt = 0; nt < 4; nt++) {
                mma_tf32(acc[mt][nt], ah[mt], bh[nt]);
                mma_tf32(acc[mt][nt], al[mt], bh[nt]);
                mma_tf32(acc[mt][nt], ah[mt], bl[nt]);
            }
        __syncthreads();
    }

#pragma unroll
    for (int mt = 0; mt < 2; mt++) {
        int row0 = bm + warp_m + mt * 16 + gid;
#pragma unroll
        for (int nt = 0; nt < 4; nt++) {
            int col = bn + warp_n + nt * 8 + 2 * tg;
            float4 v = acc[mt][nt];
            float b0 = pp.bias[col], b1 = pp.bias[col + 1];
            v.x = fmaxf(v.x + b0, 0.f); v.y = fmaxf(v.y + b1, 0.f);
            v.z = fmaxf(v.z + b0, 0.f); v.w = fmaxf(v.w + b1, 0.f);
            if (EPI == 2) {
                float2 r0 = *(const float2*)&pp.R[(size_t)row0 * N + col];
                float2 r1 = *(const float2*)&pp.R[(size_t)(row0 + 8) * N + col];
                v.x += r0.x; v.y += r0.y; v.z += r1.x; v.w += r1.y;
            }
            if (pp.C) {
                *(float2*)&pp.C[(size_t)row0 * N + col] = make_float2(v.x, v.y);
                *(float2*)&pp.C[(size_t)(row0 + 8) * N + col] = make_float2(v.z, v.w);
            }
            if (pp.Ch) {
                uint32_t hx, lx, hy, ly, hz, lz, hw, lw;
                tf_split(v.x, hx, lx); tf_split(v.y, hy, ly);
                tf_split(v.z, hz, lz); tf_split(v.w, hw, lw);
                *(uint2*)&pp.Ch[(size_t)row0 * N + col] = make_uint2(hx, hy);
                *(uint2*)&pp.Cl[(size_t)row0 * N + col] = make_uint2(lx, ly);
                *(uint2*)&pp.Ch[(size_t)(row0 + 8) * N + col] = make_uint2(hz, hw);
                *(uint2*)&pp.Cl[(size_t)(row0 + 8) * N + col] = make_uint2(lz, lw);
            }
        }
    }
}

// ---------------- trans GEMM: 128x128 tile, pre-split, pipelined, fused lse ----
__global__ __launch_bounds__(256) void gemm2_tc(
    const uint32_t* __restrict__ Ahg, const uint32_t* __restrict__ Alg,
    const uint32_t* __restrict__ Bhg, const uint32_t* __restrict__ Blg,
    float* __restrict__ C, float2* __restrict__ part)
{
    constexpr int K = 256, NIT = K / 8, BUF = 6144;   // Ah(1536) Al(1536) Bh(1536) Bl(1536)
    __shared__ uint32_t smem[2 * BUF];                 // 48 KB
    int tid = threadIdx.x, wid = tid >> 5, lane = tid & 31;
    int gid = lane >> 2, tg = lane & 3;
    int bm = blockIdx.y * 128, bn = blockIdx.x * 128;
    int warp_m = (wid & 1) * 64, warp_n = (wid >> 1) * 32;

    const uint32_t* gsrc[4]; uint32_t doff[4];
#pragma unroll
    for (int i = 0; i < 4; i++) {
        int ch = tid + i * 256;                        // 0..1023
        int mat = ch >> 8;                             // 0 Ah,1 Al,2 Bh,3 Bl
        int idx = ch & 255, r = idx >> 1, half = (idx & 1) * 4;
        const uint32_t* g = (mat == 0) ? Ahg : (mat == 1) ? Alg : (mat == 2) ? Bhg : Blg;
        int row = ((mat < 2) ? bm : bn) + r;
        gsrc[i] = g + (size_t)row * K + half;
        doff[i] = mat * 1536 + r * 12 + half;
    }
    uint32_t sbase = (uint32_t)__cvta_generic_to_shared(smem);

    float4 acc[4][4];
#pragma unroll
    for (int i = 0; i < 4; i++)
#pragma unroll
        for (int j = 0; j < 4; j++) acc[i][j] = make_float4(0.f, 0.f, 0.f, 0.f);

    {
#pragma unroll
        for (int i = 0; i < 4; i++) cpasync16(sbase + doff[i] * 4, gsrc[i]);
        cp_commit();
    }
    for (int it = 0; it < NIT; it++) {
        if (it + 1 < NIT) {
            uint32_t b = sbase + ((it + 1) & 1) * (BUF * 4);
#pragma unroll
            for (int i = 0; i < 4; i++) cpasync16(b + doff[i] * 4, gsrc[i] + (it + 1) * 8);
            cp_commit();
            cp_wait<1>();
        } else {
            cp_wait<0>();
        }
        __syncthreads();
        const uint32_t* buf = smem + (it & 1) * BUF;
        uint32_t ah[4][4], al[4][4], bh[4][2], bl[4][2];
#pragma unroll
        for (int mt = 0; mt < 4; mt++) {
            int rb = warp_m + mt * 16 + gid;
            ah[mt][0] = buf[rb * 12 + tg];           al[mt][0] = buf[1536 + rb * 12 + tg];
            ah[mt][1] = buf[(rb + 8) * 12 + tg];     al[mt][1] = buf[1536 + (rb + 8) * 12 + tg];
            ah[mt][2] = buf[rb * 12 + tg + 4];       al[mt][2] = buf[1536 + rb * 12 + tg + 4];
            ah[mt][3] = buf[(rb + 8) * 12 + tg + 4]; al[mt][3] = buf[1536 + (rb + 8) * 12 + tg + 4];
        }
#pragma unroll
        for (int nt = 0; nt < 4; nt++) {
            int cb = warp_n + nt * 8 + gid;
            bh[nt][0] = buf[3072 + cb * 12 + tg];     bl[nt][0] = buf[4608 + cb * 12 + tg];
            bh[nt][1] = buf[3072 + cb * 12 + tg + 4]; bl[nt][1] = buf[4608 + cb * 12 + tg + 4];
        }
#pragma unroll
        for (int mt = 0; mt < 4; mt++)
#pragma unroll
            for (int nt = 0; nt < 4; nt++) {
                mma_tf32(acc[mt][nt], ah[mt], bh[nt]);
                mma_tf32(acc[mt][nt], al[mt], bh[nt]);
                mma_tf32(acc[mt][nt], ah[mt], bl[nt]);
            }
        __syncthreads();
    }

    // epilogue: store C + per-row (m,s) partials over this warp's 32 cols
    int chunk = blockIdx.x * 4 + (wid >> 1);
#pragma unroll
    for (int mt = 0; mt < 4; mt++) {
        int row0 = bm + warp_m + mt * 16 + gid;
        float m0 = -CUDART_INF_F, s0 = 0.f, m8 = -CUDART_INF_F, s8 = 0.f;
#pragma unroll
        for (int nt = 0; nt < 4; nt++) {
            int col = bn + warp_n + nt * 8 + 2 * tg;
            float4 v = acc[mt][nt];
            *(float2*)&C[(size_t)row0 * Cc + col] = make_float2(v.x, v.y);
            *(float2*)&C[(size_t)(row0 + 8) * Cc + col] = make_float2(v.z, v.w);
            lse_acc(m0, s0, v.x); lse_acc(m0, s0, v.y);
            lse_acc(m8, s8, v.z); lse_acc(m8, s8, v.w);
        }
#pragma unroll
        for (int o = 1; o <= 2; o <<= 1) {
            float m2 = __shfl_xor_sync(0xffffffffu, m0, o);
            float s2 = __shfl_xor_sync(0xffffffffu, s0, o);
            lse_merge(m0, s0, m2, s2);
            m2 = __shfl_xor_sync(0xffffffffu, m8, o);
            s2 = __shfl_xor_sync(0xffffffffu, s8, o);
            lse_merge(m8, s8, m2, s2);
        }
        if (tg == 0) {
            part[(size_t)row0 * 128 + chunk] = make_float2(m0, s0);
            part[(size_t)(row0 + 8) * 128 + chunk] = make_float2(m8, s8);
        }
    }
}

// merge 128 (m,s) partials per row -> tlse
__global__ void tlsemerge_k(const float2* __restrict__ part, float* __restrict__ tlse) {
    int row = blockIdx.x * 8 + (threadIdx.x >> 5);
    int lane = threadIdx.x & 31;
    float m = -CUDART_INF_F, s = 0.f;
#pragma unroll
    for (int i = 0; i < 4; i++) {
        float2 p = part[(size_t)row * 128 + lane + 32 * i];
        lse_merge(m, s, p.x, p.y);
    }
#pragma unroll
    for (int o = 16; o > 0; o >>= 1) {
        float m2 = __shfl_xor_sync(0xffffffffu, m, o);
        float s2 = __shfl_xor_sync(0xffffffffu, s, o);
        lse_merge(m, s, m2, s2);
    }
    if (lane == 0) tlse[row] = m + __logf(s);
}

// ---------------- start head ----------------
__global__ void slog_k(const float* __restrict__ Rr, const float* __restrict__ w,
                       const float* __restrict__ b, float* __restrict__ slog) {
    int row  = blockIdx.x * 8 + (threadIdx.x >> 5);
    int lane = threadIdx.x & 31;
    const float* r = Rr + (size_t)row * Hh;
    float p = 0.f;
#pragma unroll
    for (int q = 0; q < 8; q++) p += r[lane + 32 * q] * w[lane + 32 * q];
    p = warp_sum(p);
    if (lane == 0) slog[row] = p + b[0];
}

__global__ __launch_bounds__(1024) void lse4096_k(const float* __restrict__ x, float* __restrict__ out) {
    int tid = threadIdx.x;
    float m = -CUDART_INF_F, s = 0.f;
    for (int i = tid; i < Cc; i += 1024) lse_acc(m, s, x[i]);
#pragma unroll
    for (int o = 16; o > 0; o >>= 1) {
        float m2 = __shfl_xor_sync(0xffffffffu, m, o);
        float s2 = __shfl_xor_sync(0xffffffffu, s, o);
        lse_merge(m, s, m2, s2);
    }
    __shared__ float sm[32], ss[32];
    int w = tid >> 5, lane = tid & 31;
    if (lane == 0) { sm[w] = m; ss[w] = s; }
    __syncthreads();
    if (tid == 0) {
        float M = sm[0], S = ss[0];
        for (int i = 1; i < 32; i++) lse_merge(M, S, sm[i], ss[i]);
        out[0] = M + __logf(S);
    }
}

__global__ void transpose_k(const float* __restrict__ in, float* __restrict__ out) {
    __shared__ float t[32][33];
    int bx = blockIdx.x * 32;
    int by = blockIdx.y * 32;
    int x = threadIdx.x, y = threadIdx.y;
#pragma unroll
    for (int i = 0; i < 32; i += 8)
        t[y + i][x] = in[(size_t)(by + y + i) * Vv + bx + x];
    __syncthreads();
#pragma unroll
    for (int i = 0; i < 32; i += 8)
        out[(size_t)(bx + y + i) * Hh + by + x] = t[x][y + i];
}

__global__ void initmax_k(int* __restrict__ rm, float* __restrict__ rs) {
    int i = blockIdx.x * 256 + threadIdx.x;
    if (i < Cc) { rm[i] = (int)0x80000000; rs[i] = 0.f; }
}

// sparse emission logits: block per word, float4 loads, e-column cached in regs
__global__ __launch_bounds__(256) void emlog_k(
    const float* __restrict__ pre, const float* __restrict__ ewT,
    const float* __restrict__ eb, const int* __restrict__ w2s,
    float* __restrict__ L, int* __restrict__ rowmax)
{
    int v = blockIdx.x;
    __shared__ float4 ecol4[64];
    __shared__ int st[SPW];
    int tid = threadIdx.x;
    if (tid < 64) ecol4[tid] = ((const float4*)(ewT + (size_t)v * Hh))[tid];
    if (tid >= 224) st[tid - 224] = w2s[v * SPW + (tid - 224)];
    __syncthreads();
    int w = tid >> 5, lane = tid & 31;
    float4 e0 = ecol4[lane], e1 = ecol4[lane + 32];
    float bv = eb[v];
#pragma unroll
    for (int q = 0; q < 4; q++) {
        int jj = w + q * 8;
        int c = st[jj];
        const float4* pr = (const float4*)(pre + (size_t)c * Hh);
        float4 p0 = pr[lane], p1 = pr[lane + 32];
        float p = p0.x * e0.x + p0.y * e0.y + p0.z * e0.z + p0.w * e0.w
                + p1.x * e1.x + p1.y * e1.y + p1.z * e1.z + p1.w * e1.w;
        p = warp_sum(p);
        if (lane == 0) {
            float val = p + bv;
            L[v * SPW + jj] = val;
            atomicMax(&rowmax[c], ford(val));
        }
    }
}

__global__ void emsum_k(const int* __restrict__ w2s, const float* __restrict__ L,
                        const int* __restrict__ rm, float* __restrict__ rsum) {
    int gid = blockIdx.x * 256 + threadIdx.x;
    int v = gid >> 5, j = gid & 31;
    int c = w2s[v * SPW + j];
    for (int jp = 0; jp < j; jp++)
        if (w2s[v * SPW + jp] == c) return;
    atomicAdd(&rsum[c], __expf(L[gid] - deord(rm[c])));
}

__global__ void stlse_k(const int* __restrict__ rm, const float* __restrict__ rsum,
                        float* __restrict__ stlse) {
    int i = blockIdx.x * 256 + threadIdx.x;
    if (i < Cc) stlse[i] = deord(rm[i]) + __logf(rsum[i]);
}

// phi with obs/init fused
__global__ __launch_bounds__(1024) void phi_k(
    const int* __restrict__ text, const int* __restrict__ w2s,
    const float* __restrict__ trans, const float* __restrict__ tlse,
    const float* __restrict__ L, const float* __restrict__ stlse,
    const float* __restrict__ slog, const float* __restrict__ slse,
    float* __restrict__ phi)
{
    int b = blockIdx.x;
    int n = b / Tm1, t = b % Tm1;
    __shared__ int c0[SPW], c1[SPW];
    __shared__ float ob1[SPW], iob[SPW];
    int tid = threadIdx.x;
    if (tid < SPW) {
        int v0 = text[n * Tt + t], v1 = text[n * Tt + t + 1];
        int cc0 = w2s[v0 * SPW + tid], cc1 = w2s[v1 * SPW + tid];
        c0[tid] = cc0; c1[tid] = cc1;
        ob1[tid] = L[v1 * SPW + tid] - stlse[cc1];
        iob[tid] = (t == 0)
            ? (slog[cc0] - slse[0] + L[v0 * SPW + tid] - stlse[cc0]) : 0.f;
    }
    __syncthreads();
    int k = tid >> 5, j = tid & 31;
    float val = trans[(size_t)c0[j] * Cc + c1[k]] - tlse[c0[j]] + ob1[k] + iob[j];
    phi[(size_t)(t * Nn + n) * 1024 + tid] = val;
}

// forward (blocks 0..31) / backward (32..63) scans; 1 barrier per step
__global__ __launch_bounds__(1024) void scan_k(
    const float* __restrict__ phi, float* __restrict__ ap, float* __restrict__ bn,
    float* __restrict__ logZ, float* __restrict__ out)
{
    __shared__ float a_s[2][SPW];
    int tid = threadIdx.x, w = tid >> 5, lane = tid & 31;
    bool bwd = blockIdx.x >= Nn;
    int n = bwd ? (int)blockIdx.x - Nn : (int)blockIdx.x;
    if (tid < SPW) a_s[0][tid] = 0.f;
    __syncthreads();
    int cur = 0;
    if (!bwd) {
        float pv = phi[(size_t)n * 1024 + tid];
        for (int t = 0; t < Tm1; t++) {
            float pvn = (t + 1 < Tm1) ? phi[(size_t)((t + 1) * Nn + n) * 1024 + tid] : 0.f;
            if (tid < SPW) ap[(size_t)(t * Nn + n) * SPW + tid] = a_s[cur][tid];
            float x = pv + a_s[cur][lane];
            float m = warp_max(x);
            float s = warp_sum(__expf(x - m));
            if (lane == 0) a_s[cur ^ 1][w] = m + __logf(s);
            __syncthreads();
            cur ^= 1;
            pv = pvn;
        }
        if (w == 0) {
            float x = a_s[cur][lane];
            float m = warp_max(x);
            float s = warp_sum(__expf(x - m));
            float lz = m + __logf(s);
            if (lane == 0) logZ[n] = lz;
            out[2 + n * SPW + lane] = x - lz;
        }
    } else {
        // transposed phi read: thread (w=j, lane=k) reads phi[t][k=lane][j=w]
        float pv = phi[(size_t)((Tm1 - 1) * Nn + n) * 1024 + lane * SPW + w];
        for (int t = Tm1 - 1; t >= 0; t--) {
            float pvn = (t > 0) ? phi[(size_t)((t - 1) * Nn + n) * 1024 + lane * SPW + w] : 0.f;
            if (tid < SPW) bn[(size_t)(t * Nn + n) * SPW + tid] = a_s[cur][tid];
            float x = pv + a_s[cur][lane];
            float m = warp_max(x);
            float s = warp_sum(__expf(x - m));
            if (lane == 0) a_s[cur ^ 1][w] = m + __logf(s);
            __syncthreads();
            cur ^= 1;
            pv = pvn;
        }
    }
}

__global__ void evid_k(const float* __restrict__ logZ, float* __restrict__ out) {
    if (threadIdx.x == 0) {
        float s = 0.f;
        for (int i = 0; i < Nn; i++) s += logZ[i];
        out[1] = s;
        out[0] = 0.f;
    }
}

__global__ __launch_bounds__(1024) void elbo_k(
    const float* __restrict__ phi, const float* __restrict__ ap,
    const float* __restrict__ bn, const float* __restrict__ logZ,
    float* __restrict__ out)
{
    int e = blockIdx.x;
    int n = e % Nn;
    __shared__ float sap[SPW], sbn[SPW], ws[32];
    int tid = threadIdx.x;
    if (tid < SPW) { sap[tid] = ap[(size_t)e * SPW + tid]; sbn[tid] = bn[(size_t)e * SPW + tid]; }
    __syncthreads();
    int k = tid >> 5, j = tid & 31;
    float p = phi[(size_t)e * 1024 + tid];
    float term = __expf(sap[j] + p + sbn[k] - logZ[n]) * p;
    term = warp_sum(term);
    if (j == 0) ws[k] = term;
    __syncthreads();
    if (tid < 32) {
        float v = warp_sum(ws[tid]);
        if (tid == 0) atomicAdd(&out[0], v);
    }
}

// ---------------- launcher ----------------
extern "C" void kernel_launch(void* const* d_in, const int* in_sizes, int n_in,
                              void* d_out, int out_size) {
    const float* start_emb = (const float*)d_in[0];
    const float* sw1  = (const float*)d_in[1];
    const float* sb1  = (const float*)d_in[2];
    const float* sw2  = (const float*)d_in[3];
    const float* sb2  = (const float*)d_in[4];
    const float* s_out_w = (const float*)d_in[5];
    const float* s_out_b = (const float*)d_in[6];
    const float* state_emb = (const float*)d_in[7];
    const float* tw1  = (const float*)d_in[8];
    const float* tb1  = (const float*)d_in[9];
    const float* tw2  = (const float*)d_in[10];
    const float* tb2  = (const float*)d_in[11];
    const float* nsp  = (const float*)d_in[12];
    const float* pre_emb = (const float*)d_in[13];
    const float* ew1  = (const float*)d_in[14];
    const float* eb1  = (const float*)d_in[15];
    const float* ew2  = (const float*)d_in[16];
    const float* eb2  = (const float*)d_in[17];
    const float* e_out_w = (const float*)d_in[18];
    const float* e_out_b = (const float*)d_in[19];
    const int* text = (const int*)d_in[20];
    const int* w2s  = (const int*)d_in[21];
    float* out = (float*)d_out;

    float* S = nullptr; int* RM = nullptr; uint32_t* U = nullptr;
    cudaGetSymbolAddress((void**)&S, g_scr);
    cudaGetSymbolAddress((void**)&RM, g_rowmax);
    cudaGetSymbolAddress((void**)&U, g_u);

    static bool inited = false;
    static cudaStream_t s1, s2;
    static cudaEvent_t evStart, evW, evB2, evEm, evS;
    if (!inited) {
        cudaStreamCreateWithFlags(&s1, cudaStreamNonBlocking);
        cudaStreamCreateWithFlags(&s2, cudaStreamNonBlocking);
        cudaEventCreateWithFlags(&evStart, cudaEventDisableTiming);
        cudaEventCreateWithFlags(&evW, cudaEventDisableTiming);
        cudaEventCreateWithFlags(&evB2, cudaEventDisableTiming);
        cudaEventCreateWithFlags(&evEm, cudaEventDisableTiming);
        cudaEventCreateWithFlags(&evS, cudaEventDisableTiming);
        inited = true;
    }

    cudaEventRecord(evStart, 0);
    cudaStreamWaitEvent(s1, evStart, 0);

    // ---- s1: weight transpose+split, ewT transpose, rowmax init ----
    WP6 wb;
    const float* ws_[6] = { sw1, tw1, ew1, sw2, tw2, ew2 };
    for (int j = 0; j < 6; j++)
        wb.p[j] = { ws_[j], U + UWB + (size_t)j * 2 * WSZ, U + UWB + (size_t)j * 2 * WSZ + WSZ };
    wtsplit_k<<<dim3(8, 8, 6), dim3(32, 8), 0, s1>>>(wb);
    cudaEventRecord(evW, s1);
    transpose_k<<<dim3(Vv / 32, Hh / 32), dim3(32, 8), 0, s1>>>(e_out_w, S + OFF_EWT);
    initmax_k<<<16, 256, 0, s1>>>(RM, S + OFF_RSUM);

    // ---- main: all presplits (3 embeddings + nsp) in one launch ----
    SP4 sp;
    const float* em_[3] = { start_emb, state_emb, pre_emb };
    for (int j = 0; j < 3; j++)
        sp.p[j] = { em_[j], U + UEMB + (size_t)j * 2 * SZ_MAT, U + UEMB + (size_t)j * 2 * SZ_MAT + SZ_MAT };
    sp.p[3] = { nsp, U + UBH, U + UBL };
    presplit4_k<<<dim3(SZ_MAT / 4 / 256, 1, 4), 256>>>(sp);
    cudaStreamWaitEvent(0, evW, 0);

    // ---- main: MLPs ----
    const float* b1_[3] = { sb1, tb1, eb1 };
    PP3 m1;
    for (int j = 0; j < 3; j++)
        m1.p[j] = { U + UEMB + (size_t)j * 2 * SZ_MAT, U + UEMB + (size_t)j * 2 * SZ_MAT + SZ_MAT,
                    U + UWB + (size_t)j * 2 * WSZ, U + UWB + (size_t)j * 2 * WSZ + WSZ,
                    b1_[j], nullptr, nullptr,
                    U + UHB + (size_t)j * 2 * SZ_MAT, U + UHB + (size_t)j * 2 * SZ_MAT + SZ_MAT };
    gemmp<1><<<dim3(Hh / 64, Cc / 128, 3), 256>>>(m1, Hh);

    PP3 m2;
    m2.p[0] = { U + UHB + 0 * SZ_MAT, U + UHB + 1 * SZ_MAT,
                U + UWB + 3 * 2 * WSZ, U + UWB + 3 * 2 * WSZ + WSZ,
                sb2, start_emb, S + OFF_RS, nullptr, nullptr };
    m2.p[1] = { U + UHB + 2 * SZ_MAT, U + UHB + 3 * SZ_MAT,
                U + UWB + 4 * 2 * WSZ, U + UWB + 4 * 2 * WSZ + WSZ,
                tb2, state_emb, nullptr, U + UAH, U + UAL };
    m2.p[2] = { U + UHB + 4 * SZ_MAT, U + UHB + 5 * SZ_MAT,
                U + UWB + 5 * 2 * WSZ, U + UWB + 5 * 2 * WSZ + WSZ,
                eb2, pre_emb, S + OFF_RP, nullptr, nullptr };
    gemmp<2><<<dim3(Hh / 64, Cc / 128, 3), 256>>>(m2, Hh);
    cudaEventRecord(evB2, 0);

    // ---- s2: start head ----
    cudaStreamWaitEvent(s2, evB2, 0);
    slog_k<<<Cc / 8, 256, 0, s2>>>(S + OFF_RS, s_out_w, s_out_b, S + OFF_SLOG);
    lse4096_k<<<1, 1024, 0, s2>>>(S + OFF_SLOG, S + OFF_SLSE);
    cudaEventRecord(evS, s2);

    // ---- s1: emission chain ----
    cudaStreamWaitEvent(s1, evB2, 0);
    emlog_k<<<Vv, 256, 0, s1>>>(S + OFF_RP, S + OFF_EWT, e_out_b, w2s, S + OFF_L, RM);
    emsum_k<<<Vv * SPW / 256, 256, 0, s1>>>(w2s, S + OFF_L, RM, S + OFF_RSUM);
    stlse_k<<<16, 256, 0, s1>>>(RM, S + OFF_RSUM, S + OFF_STLSE);
    cudaEventRecord(evEm, s1);

    // ---- main: trans GEMM (128x128 tiles) + fused row-lse ----
    gemm2_tc<<<dim3(Cc / 128, Cc / 128), 256>>>(U + UAH, U + UAL, U + UBH, U + UBL,
                                                S + OFF_TRANS, (float2*)(S + OFF_PART));
    tlsemerge_k<<<Cc / 8, 256>>>((float2*)(S + OFF_PART), S + OFF_TLSE);

    // ---- join + tail ----
    cudaStreamWaitEvent(0, evEm, 0);
    cudaStreamWaitEvent(0, evS, 0);
    phi_k<<<Nn * Tm1, 1024>>>(text, w2s, S + OFF_TRANS, S + OFF_TLSE,
                              S + OFF_L, S + OFF_STLSE, S + OFF_SLOG, S + OFF_SLSE,
                              S + OFF_PHI);
    scan_k<<<2 * Nn, 1024>>>(S + OFF_PHI, S + OFF_AP, S + OFF_BN, S + OFF_LOGZ, out);
    evid_k<<<1, 32>>>(S + OFF_LOGZ, out);
    elbo_k<<<Tm1 * Nn, 1024>>>(S + OFF_PHI, S + OFF_AP, S + OFF_BN, S + OFF_LOGZ, out);
}

// round 6
// speedup vs baseline: 1.0375x; 1.0375x over previous
#include <cuda_runtime.h>
#include <math_constants.h>
#include <cstdint>
#include <cstddef>

static constexpr int Vv = 16000, Cc = 4096, Hh = 256, SPW = 32, Nn = 32, Tt = 128, Tm1 = 127;

// ---------------- scratch layout ----------------
constexpr size_t SZ_MAT   = (size_t)Cc * Hh;                  // 1,048,576
constexpr size_t OFF_RS   = 0;
constexpr size_t OFF_RP   = OFF_RS   + SZ_MAT;
constexpr size_t OFF_TRANS= OFF_RP   + SZ_MAT;                // 4096x4096
constexpr size_t OFF_TLSE = OFF_TRANS+ (size_t)Cc * Cc;
constexpr size_t OFF_SLOG = OFF_TLSE + Cc;
constexpr size_t OFF_SLSE = OFF_SLOG + Cc;
constexpr size_t OFF_EWT  = OFF_SLSE + 32;                    // V x H
constexpr size_t OFF_L    = OFF_EWT  + (size_t)Vv * Hh;       // V x SPW
constexpr size_t OFF_RSUM = OFF_L    + (size_t)Vv * SPW;
constexpr size_t OFF_STLSE= OFF_RSUM + Cc;
constexpr size_t OFF_PHI  = OFF_STLSE+ Cc;                    // Tm1*N*32*32
constexpr size_t OFF_AP   = OFF_PHI  + (size_t)Tm1 * Nn * SPW * SPW;
constexpr size_t OFF_BN   = OFF_AP   + (size_t)Tm1 * Nn * SPW;
constexpr size_t OFF_LOGZ = OFF_BN   + (size_t)Tm1 * Nn * SPW;
constexpr size_t OFF_PART = OFF_LOGZ + 64;                    // 4096 x 128 x (m,s)
constexpr size_t SCRATCH_TOTAL = OFF_PART + (size_t)Cc * 128 * 2;

__device__ float g_scr[SCRATCH_TOTAL];
__device__ int   g_rowmax[Cc];

// tf32 hi/lo split buffers (u32 elements)
constexpr size_t WSZ = (size_t)Hh * Hh;                       // 65536
constexpr size_t UAH = 0, UAL = SZ_MAT;                       // RST split
constexpr size_t UBH = 2 * SZ_MAT, UBL = 3 * SZ_MAT;          // nsp split
constexpr size_t UEMB = 4 * SZ_MAT;                           // 3 x (hi,lo) embeddings
constexpr size_t UHB  = 10 * SZ_MAT;                          // 3 x (hi,lo) H outputs
constexpr size_t UWB  = 16 * SZ_MAT;                          // 6 x (hi,lo) weights
__device__ uint32_t g_u[16 * SZ_MAT + 12 * WSZ];

// ---------------- helpers ----------------
__device__ __forceinline__ int ford(float f) {
    int i = __float_as_int(f);
    return i >= 0 ? i : (i ^ 0x7fffffff);
}
__device__ __forceinline__ float deord(int i) {
    return __int_as_float(i >= 0 ? i : (i ^ 0x7fffffff));
}
__device__ __forceinline__ void lse_acc(float& m, float& s, float v) {
    if (v > m) { s = s * __expf(m - v) + 1.f; m = v; }
    else       { s += __expf(v - m); }
}
__device__ __forceinline__ void lse_merge(float& m, float& s, float m2, float s2) {
    if (m2 > m) { s = s * __expf(m - m2) + s2; m = m2; }
    else        { s += s2 * __expf(m2 - m); }
}
__device__ __forceinline__ float warp_sum(float v) {
#pragma unroll
    for (int o = 16; o > 0; o >>= 1) v += __shfl_xor_sync(0xffffffffu, v, o);
    return v;
}
__device__ __forceinline__ float warp_max(float v) {
#pragma unroll
    for (int o = 16; o > 0; o >>= 1) v = fmaxf(v, __shfl_xor_sync(0xffffffffu, v, o));
    return v;
}

// ---------------- tf32 utils ----------------
__device__ __forceinline__ uint32_t f2tf(float x) {
    uint32_t r;
    asm("cvt.rna.tf32.f32 %0, %1;" : "=r"(r) : "f"(x));
    return r;
}
__device__ __forceinline__ void tf_split(float x, uint32_t& hi, uint32_t& lo) {
    hi = f2tf(x);
    lo = f2tf(x - __uint_as_float(hi));
}
__device__ __forceinline__ void mma_tf32(float4& d, const uint32_t* a, const uint32_t* b) {
    asm volatile(
        "mma.sync.aligned.m16n8k8.row.col.f32.tf32.tf32.f32 "
        "{%0,%1,%2,%3}, {%4,%5,%6,%7}, {%8,%9}, {%0,%1,%2,%3};"
        : "+f"(d.x), "+f"(d.y), "+f"(d.z), "+f"(d.w)
        : "r"(a[0]), "r"(a[1]), "r"(a[2]), "r"(a[3]), "r"(b[0]), "r"(b[1]));
}
__device__ __forceinline__ void cpasync16(uint32_t dst, const void* src) {
    asm volatile("cp.async.cg.shared.global [%0], [%1], 16;" :: "r"(dst), "l"(src));
}
__device__ __forceinline__ void cp_commit() { asm volatile("cp.async.commit_group;"); }
template <int N> __device__ __forceinline__ void cp_wait() {
    asm volatile("cp.async.wait_group %0;" :: "n"(N));
}

// ---------------- unified prep kernel ----------------
// blocks [0,4096): presplit 4 matrices; [4096,4480): wt transpose+split x6;
// [4480,8480): ewT transpose; [8480,8512): init rowmax/rsum/slog.
struct Prep {
    const float* psrc[4]; uint32_t* phid[4]; uint32_t* plod[4];
    const float* wsrc[6]; uint32_t* whid[6]; uint32_t* wlod[6];
    const float* ew; float* ewt;
    int* rm; float* rsum; float* slg; const float* soutb;
};
__global__ __launch_bounds__(256) void prep_k(Prep P) {
    __shared__ float t[32][33];
    int b = blockIdx.x, tid = threadIdx.x;
    if (b < 4096) {
        int mat = b >> 10;
        int i = (b & 1023) * 256 + tid;
        float4 v = ((const float4*)P.psrc[mat])[i];
        uint4 h, l;
        tf_split(v.x, h.x, l.x); tf_split(v.y, h.y, l.y);
        tf_split(v.z, h.z, l.z); tf_split(v.w, h.w, l.w);
        ((uint4*)P.phid[mat])[i] = h; ((uint4*)P.plod[mat])[i] = l;
    } else if (b < 4480) {
        int idx = b - 4096;
        int mat = idx >> 6, p = idx & 63;
        int bx = (p & 7) * 32, by = (p >> 3) * 32;
        int x = tid & 31, y = tid >> 5;
        const float* w = P.wsrc[mat];
#pragma unroll
        for (int i = 0; i < 32; i += 8)
            t[y + i][x] = w[(size_t)(by + y + i) * Hh + bx + x];
        __syncthreads();
#pragma unroll
        for (int i = 0; i < 32; i += 8) {
            float v = t[x][y + i];
            uint32_t h, l;
            tf_split(v, h, l);
            P.whid[mat][(size_t)(bx + y + i) * Hh + by + x] = h;
            P.wlod[mat][(size_t)(bx + y + i) * Hh + by + x] = l;
        }
    } else if (b < 8480) {
        int p = b - 4480;
        int bx = (p % 500) * 32, by = (p / 500) * 32;
        int x = tid & 31, y = tid >> 5;
#pragma unroll
        for (int i = 0; i < 32; i += 8)
            t[y + i][x] = P.ew[(size_t)(by + y + i) * Vv + bx + x];
        __syncthreads();
#pragma unroll
        for (int i = 0; i < 32; i += 8)
            P.ewt[(size_t)(bx + y + i) * Hh + by + x] = t[x][y + i];
    } else {
        int i = (b - 8480) * 256 + tid;
        if (i < Cc) { P.rm[i] = (int)0x80000000; P.rsum[i] = 0.f; }
        else        { P.slg[i - Cc] = P.soutb[0]; }
    }
}

// ---------------- MLP GEMM: 128x64 tile pipelined pre-split -------
struct PP { const uint32_t *Ah, *Al, *Bh, *Bl; const float *bias, *R, *sw;
            float *C; uint32_t *Ch, *Cl; };
struct PP3 { PP p[3]; };

template <int EPI>
__global__ __launch_bounds__(256) void gemmp(PP3 bt, float* __restrict__ slogp, int N) {
    constexpr int K = 256, NIT = K / 8, BUF = 4608;
    __shared__ uint32_t smem[2 * BUF];
    const PP pp = bt.p[blockIdx.z];
    int tid = threadIdx.x, wid = tid >> 5, lane = tid & 31;
    int gid = lane >> 2, tg = lane & 3;
    int bm = blockIdx.y * 128, bn = blockIdx.x * 64;
    int warp_m = (wid & 3) * 32, warp_n = (wid >> 2) * 32;

    const uint32_t* gsrc[3]; uint32_t doff[3];
#pragma unroll
    for (int i = 0; i < 3; i++) {
        int ch = tid + i * 256;
        if (ch < 512) {
            int mat = ch >> 8, r = (ch >> 1) & 127, c4 = (ch & 1) * 4;
            gsrc[i] = (mat ? pp.Al : pp.Ah) + (size_t)(bm + r) * K + c4;
            doff[i] = mat * 1536 + r * 12 + c4;
        } else {
            int idx = ch - 512;
            int mat = idx >> 7, r = (idx >> 1) & 63, c4 = (idx & 1) * 4;
            gsrc[i] = (mat ? pp.Bl : pp.Bh) + (size_t)(bn + r) * K + c4;
            doff[i] = 3072 + mat * 768 + r * 12 + c4;
        }
    }
    uint32_t sbase = (uint32_t)__cvta_generic_to_shared(smem);

    float4 acc[2][4];
#pragma unroll
    for (int i = 0; i < 2; i++)
#pragma unroll
        for (int j = 0; j < 4; j++) acc[i][j] = make_float4(0.f, 0.f, 0.f, 0.f);

    {
#pragma unroll
        for (int i = 0; i < 3; i++) cpasync16(sbase + doff[i] * 4, gsrc[i]);
        cp_commit();
    }
    for (int it = 0; it < NIT; it++) {
        if (it + 1 < NIT) {
            uint32_t b = sbase + ((it + 1) & 1) * (BUF * 4);
#pragma unroll
            for (int i = 0; i < 3; i++) cpasync16(b + doff[i] * 4, gsrc[i] + (it + 1) * 8);
            cp_commit();
            cp_wait<1>();
        } else {
            cp_wait<0>();
        }
        __syncthreads();
        const uint32_t* buf = smem + (it & 1) * BUF;
        uint32_t ah[2][4], al[2][4], bh[4][2], bl[4][2];
#pragma unroll
        for (int mt = 0; mt < 2; mt++) {
            int rb = warp_m + mt * 16 + gid;
            ah[mt][0] = buf[rb * 12 + tg];           al[mt][0] = buf[1536 + rb * 12 + tg];
            ah[mt][1] = buf[(rb + 8) * 12 + tg];     al[mt][1] = buf[1536 + (rb + 8) * 12 + tg];
            ah[mt][2] = buf[rb * 12 + tg + 4];       al[mt][2] = buf[1536 + rb * 12 + tg + 4];
            ah[mt][3] = buf[(rb + 8) * 12 + tg + 4]; al[mt][3] = buf[1536 + (rb + 8) * 12 + tg + 4];
        }
#pragma unroll
        for (int nt = 0; nt < 4; nt++) {
            int cb = warp_n + nt * 8 + gid;
            bh[nt][0] = buf[3072 + cb * 12 + tg];     bl[nt][0] = buf[3840 + cb * 12 + tg];
            bh[nt][1] = buf[3072 + cb * 12 + tg + 4]; bl[nt][1] = buf[3840 + cb * 12 + tg + 4];
        }
#pragma unroll
        for (int mt = 0; mt < 2; mt++)
#pragma unroll
            for (int nt = 0; nt < 4; nt++) {
                mma_tf32(acc[mt][nt], ah[mt], bh[nt]);
                mma_tf32(acc[mt][nt], al[mt], bh[nt]);
                mma_tf32(acc[mt][nt], ah[mt], bl[nt]);
            }
        __syncthreads();
    }

#pragma unroll
    for (int mt = 0; mt < 2; mt++) {
        int row0 = bm + warp_m + mt * 16 + gid;
        float pr0 = 0.f, pr8 = 0.f;
#pragma unroll
        for (int nt = 0; nt < 4; nt++) {
            int col = bn + warp_n + nt * 8 + 2 * tg;
            float4 v = acc[mt][nt];
            float b0 = pp.bias[col], b1 = pp.bias[col + 1];
            v.x = fmaxf(v.x + b0, 0.f); v.y = fmaxf(v.y + b1, 0.f);
            v.z = fmaxf(v.z + b0, 0.f); v.w = fmaxf(v.w + b1, 0.f);
            if (EPI == 2) {
                float2 r0 = *(const float2*)&pp.R[(size_t)row0 * N + col];
                float2 r1 = *(const float2*)&pp.R[(size_t)(row0 + 8) * N + col];
                v.x += r0.x; v.y += r0.y; v.z += r1.x; v.w += r1.y;
                if (pp.sw) {
                    float w0 = pp.sw[col], w1 = pp.sw[col + 1];
                    pr0 += v.x * w0 + v.y * w1;
                    pr8 += v.z * w0 + v.w * w1;
                }
            }
            if (pp.C) {
                *(float2*)&pp.C[(size_t)row0 * N + col] = make_float2(v.x, v.y);
                *(float2*)&pp.C[(size_t)(row0 + 8) * N + col] = make_float2(v.z, v.w);
            }
            if (pp.Ch) {
                uint32_t hx, lx, hy, ly, hz, lz, hw, lw;
                tf_split(v.x, hx, lx); tf_split(v.y, hy, ly);
                tf_split(v.z, hz, lz); tf_split(v.w, hw, lw);
                *(uint2*)&pp.Ch[(size_t)row0 * N + col] = make_uint2(hx, hy);
                *(uint2*)&pp.Cl[(size_t)row0 * N + col] = make_uint2(lx, ly);
                *(uint2*)&pp.Ch[(size_t)(row0 + 8) * N + col] = make_uint2(hz, hw);
                *(uint2*)&pp.Cl[(size_t)(row0 + 8) * N + col] = make_uint2(lz, lw);
            }
        }
        if (EPI == 2 && pp.sw) {
            pr0 += __shfl_xor_sync(0xffffffffu, pr0, 1);
            pr0 += __shfl_xor_sync(0xffffffffu, pr0, 2);
            pr8 += __shfl_xor_sync(0xffffffffu, pr8, 1);
            pr8 += __shfl_xor_sync(0xffffffffu, pr8, 2);
            if (tg == 0) {
                atomicAdd(&slogp[row0], pr0);
                atomicAdd(&slogp[row0 + 8], pr8);
            }
        }
    }
}

// ---------------- trans GEMM: 128x128 tile, pre-split, pipelined, fused lse ----
__global__ __launch_bounds__(256) void gemm2_tc(
    const uint32_t* __restrict__ Ahg, const uint32_t* __restrict__ Alg,
    const uint32_t* __restrict__ Bhg, const uint32_t* __restrict__ Blg,
    float* __restrict__ C, float2* __restrict__ part)
{
    constexpr int K = 256, NIT = K / 8, BUF = 6144;
    __shared__ uint32_t smem[2 * BUF];
    int tid = threadIdx.x, wid = tid >> 5, lane = tid & 31;
    int gid = lane >> 2, tg = lane & 3;
    int bm = blockIdx.y * 128, bn = blockIdx.x * 128;
    int warp_m = (wid & 1) * 64, warp_n = (wid >> 1) * 32;

    const uint32_t* gsrc[4]; uint32_t doff[4];
#pragma unroll
    for (int i = 0; i < 4; i++) {
        int ch = tid + i * 256;
        int mat = ch >> 8;
        int idx = ch & 255, r = idx >> 1, half = (idx & 1) * 4;
        const uint32_t* g = (mat == 0) ? Ahg : (mat == 1) ? Alg : (mat == 2) ? Bhg : Blg;
        int row = ((mat < 2) ? bm : bn) + r;
        gsrc[i] = g + (size_t)row * K + half;
        doff[i] = mat * 1536 + r * 12 + half;
    }
    uint32_t sbase = (uint32_t)__cvta_generic_to_shared(smem);

    float4 acc[4][4];
#pragma unroll
    for (int i = 0; i < 4; i++)
#pragma unroll
        for (int j = 0; j < 4; j++) acc[i][j] = make_float4(0.f, 0.f, 0.f, 0.f);

    {
#pragma unroll
        for (int i = 0; i < 4; i++) cpasync16(sbase + doff[i] * 4, gsrc[i]);
        cp_commit();
    }
    for (int it = 0; it < NIT; it++) {
        if (it + 1 < NIT) {
            uint32_t b = sbase + ((it + 1) & 1) * (BUF * 4);
#pragma unroll
            for (int i = 0; i < 4; i++) cpasync16(b + doff[i] * 4, gsrc[i] + (it + 1) * 8);
            cp_commit();
            cp_wait<1>();
        } else {
            cp_wait<0>();
        }
        __syncthreads();
        const uint32_t* buf = smem + (it & 1) * BUF;
        uint32_t ah[4][4], al[4][4], bh[4][2], bl[4][2];
#pragma unroll
        for (int mt = 0; mt < 4; mt++) {
            int rb = warp_m + mt * 16 + gid;
            ah[mt][0] = buf[rb * 12 + tg];           al[mt][0] = buf[1536 + rb * 12 + tg];
            ah[mt][1] = buf[(rb + 8) * 12 + tg];     al[mt][1] = buf[1536 + (rb + 8) * 12 + tg];
            ah[mt][2] = buf[rb * 12 + tg + 4];       al[mt][2] = buf[1536 + rb * 12 + tg + 4];
            ah[mt][3] = buf[(rb + 8) * 12 + tg + 4]; al[mt][3] = buf[1536 + (rb + 8) * 12 + tg + 4];
        }
#pragma unroll
        for (int nt = 0; nt < 4; nt++) {
            int cb = warp_n + nt * 8 + gid;
            bh[nt][0] = buf[3072 + cb * 12 + tg];     bl[nt][0] = buf[4608 + cb * 12 + tg];
            bh[nt][1] = buf[3072 + cb * 12 + tg + 4]; bl[nt][1] = buf[4608 + cb * 12 + tg + 4];
        }
#pragma unroll
        for (int mt = 0; mt < 4; mt++)
#pragma unroll
            for (int nt = 0; nt < 4; nt++) {
                mma_tf32(acc[mt][nt], ah[mt], bh[nt]);
                mma_tf32(acc[mt][nt], al[mt], bh[nt]);
                mma_tf32(acc[mt][nt], ah[mt], bl[nt]);
            }
        __syncthreads();
    }

    int chunk = blockIdx.x * 4 + (wid >> 1);
#pragma unroll
    for (int mt = 0; mt < 4; mt++) {
        int row0 = bm + warp_m + mt * 16 + gid;
        float m0 = -CUDART_INF_F, s0 = 0.f, m8 = -CUDART_INF_F, s8 = 0.f;
#pragma unroll
        for (int nt = 0; nt < 4; nt++) {
            int col = bn + warp_n + nt * 8 + 2 * tg;
            float4 v = acc[mt][nt];
            *(float2*)&C[(size_t)row0 * Cc + col] = make_float2(v.x, v.y);
            *(float2*)&C[(size_t)(row0 + 8) * Cc + col] = make_float2(v.z, v.w);
            lse_acc(m0, s0, v.x); lse_acc(m0, s0, v.y);
            lse_acc(m8, s8, v.z); lse_acc(m8, s8, v.w);
        }
#pragma unroll
        for (int o = 1; o <= 2; o <<= 1) {
            float m2 = __shfl_xor_sync(0xffffffffu, m0, o);
            float s2 = __shfl_xor_sync(0xffffffffu, s0, o);
            lse_merge(m0, s0, m2, s2);
            m2 = __shfl_xor_sync(0xffffffffu, m8, o);
            s2 = __shfl_xor_sync(0xffffffffu, s8, o);
            lse_merge(m8, s8, m2, s2);
        }
        if (tg == 0) {
            part[(size_t)row0 * 128 + chunk] = make_float2(m0, s0);
            part[(size_t)(row0 + 8) * 128 + chunk] = make_float2(m8, s8);
        }
    }
}

// merge: blocks [0,512) tlse rows; block 512 computes slse from slog
__global__ void merge_k(const float2* __restrict__ part, float* __restrict__ tlse,
                        const float* __restrict__ slog, float* __restrict__ slse) {
    int tid = threadIdx.x;
    if (blockIdx.x < 512) {
        int row = blockIdx.x * 8 + (tid >> 5);
        int lane = tid & 31;
        float m = -CUDART_INF_F, s = 0.f;
#pragma unroll
        for (int i = 0; i < 4; i++) {
            float2 p = part[(size_t)row * 128 + lane + 32 * i];
            lse_merge(m, s, p.x, p.y);
        }
#pragma unroll
        for (int o = 16; o > 0; o >>= 1) {
            float m2 = __shfl_xor_sync(0xffffffffu, m, o);
            float s2 = __shfl_xor_sync(0xffffffffu, s, o);
            lse_merge(m, s, m2, s2);
        }
        if (lane == 0) tlse[row] = m + __logf(s);
    } else {
        float m = -CUDART_INF_F, s = 0.f;
        for (int i = tid; i < Cc; i += 256) lse_acc(m, s, slog[i]);
#pragma unroll
        for (int o = 16; o > 0; o >>= 1) {
            float m2 = __shfl_xor_sync(0xffffffffu, m, o);
            float s2 = __shfl_xor_sync(0xffffffffu, s, o);
            lse_merge(m, s, m2, s2);
        }
        __shared__ float sm[8], ss[8];
        int w = tid >> 5, lane = tid & 31;
        if (lane == 0) { sm[w] = m; ss[w] = s; }
        __syncthreads();
        if (tid == 0) {
            float M = sm[0], S = ss[0];
            for (int i = 1; i < 8; i++) lse_merge(M, S, sm[i], ss[i]);
            slse[0] = M + __logf(S);
        }
    }
}

// sparse emission logits
__global__ __launch_bounds__(256) void emlog_k(
    const float* __restrict__ pre, const float* __restrict__ ewT,
    const float* __restrict__ eb, const int* __restrict__ w2s,
    float* __restrict__ L, int* __restrict__ rowmax)
{
    int v = blockIdx.x;
    __shared__ float4 ecol4[64];
    __shared__ int st[SPW];
    int tid = threadIdx.x;
    if (tid < 64) ecol4[tid] = ((const float4*)(ewT + (size_t)v * Hh))[tid];
    if (tid >= 224) st[tid - 224] = w2s[v * SPW + (tid - 224)];
    __syncthreads();
    int w = tid >> 5, lane = tid & 31;
    float4 e0 = ecol4[lane], e1 = ecol4[lane + 32];
    float bv = eb[v];
#pragma unroll
    for (int q = 0; q < 4; q++) {
        int jj = w + q * 8;
        int c = st[jj];
        const float4* pr = (const float4*)(pre + (size_t)c * Hh);
        float4 p0 = pr[lane], p1 = pr[lane + 32];
        float p = p0.x * e0.x + p0.y * e0.y + p0.z * e0.z + p0.w * e0.w
                + p1.x * e1.x + p1.y * e1.y + p1.z * e1.z + p1.w * e1.w;
        p = warp_sum(p);
        if (lane == 0) {
            float val = p + bv;
            L[v * SPW + jj] = val;
            atomicMax(&rowmax[c], ford(val));
        }
    }
}

__global__ void emsum_k(const int* __restrict__ w2s, const float* __restrict__ L,
                        const int* __restrict__ rm, float* __restrict__ rsum) {
    int gid = blockIdx.x * 256 + threadIdx.x;
    int v = gid >> 5, j = gid & 31;
    int c = w2s[v * SPW + j];
    for (int jp = 0; jp < j; jp++)
        if (w2s[v * SPW + jp] == c) return;
    atomicAdd(&rsum[c], __expf(L[gid] - deord(rm[c])));
}

__global__ void stlse_k(const int* __restrict__ rm, const float* __restrict__ rsum,
                        float* __restrict__ stlse) {
    int i = blockIdx.x * 256 + threadIdx.x;
    if (i < Cc) stlse[i] = deord(rm[i]) + __logf(rsum[i]);
}

// phi with obs/init fused; warp-per-row gather + smem transpose, coalesced write
__global__ __launch_bounds__(1024) void phi_k(
    const int* __restrict__ text, const int* __restrict__ w2s,
    const float* __restrict__ trans, const float* __restrict__ tlse,
    const float* __restrict__ L, const float* __restrict__ stlse,
    const float* __restrict__ slog, const float* __restrict__ slse,
    float* __restrict__ phi)
{
    int b = blockIdx.x;
    int n = b / Tm1, t = b % Tm1;
    __shared__ int c0[SPW], c1[SPW];
    __shared__ float ob1[SPW], iob[SPW], tl0[SPW];
    __shared__ float tile[SPW * 33];
    int tid = threadIdx.x;
    if (tid < SPW) {
        int v0 = text[n * Tt + t], v1 = text[n * Tt + t + 1];
        int cc0 = w2s[v0 * SPW + tid], cc1 = w2s[v1 * SPW + tid];
        c0[tid] = cc0; c1[tid] = cc1;
        tl0[tid] = tlse[cc0];
        ob1[tid] = L[v1 * SPW + tid] - stlse[cc1];
        iob[tid] = (t == 0)
            ? (slog[cc0] - slse[0] + L[v0 * SPW + tid] - stlse[cc0]) : 0.f;
    }
    __syncthreads();
    int jw = tid >> 5, kl = tid & 31;          // warp = j (trans row), lane = k (col)
    float val = __ldg(&trans[(size_t)c0[jw] * Cc + c1[kl]]) - tl0[jw] + ob1[kl] + iob[jw];
    tile[jw * 33 + kl] = val;
    __syncthreads();
    int kw = tid >> 5, jl = tid & 31;
    phi[(size_t)(t * Nn + n) * 1024 + kw * SPW + jl] = tile[jl * 33 + kw];
}

// forward (blocks 0..31) / backward (32..63) scans; 1 barrier per step
__global__ __launch_bounds__(1024) void scan_k(
    const float* __restrict__ phi, float* __restrict__ ap, float* __restrict__ bn,
    float* __restrict__ logZ, float* __restrict__ out)
{
    __shared__ float a_s[2][SPW];
    int tid = threadIdx.x, w = tid >> 5, lane = tid & 31;
    bool bwd = blockIdx.x >= Nn;
    int n = bwd ? (int)blockIdx.x - Nn : (int)blockIdx.x;
    if (tid < SPW) a_s[0][tid] = 0.f;
    __syncthreads();
    int cur = 0;
    if (!bwd) {
        float pv = phi[(size_t)n * 1024 + tid];
        for (int t = 0; t < Tm1; t++) {
            float pvn = (t + 1 < Tm1) ? phi[(size_t)((t + 1) * Nn + n) * 1024 + tid] : 0.f;
            if (tid < SPW) ap[(size_t)(t * Nn + n) * SPW + tid] = a_s[cur][tid];
            float x = pv + a_s[cur][lane];
            float m = warp_max(x);
            float s = warp_sum(__expf(x - m));
            if (lane == 0) a_s[cur ^ 1][w] = m + __logf(s);
            __syncthreads();
            cur ^= 1;
            pv = pvn;
        }
        if (w == 0) {
            float x = a_s[cur][lane];
            float m = warp_max(x);
            float s = warp_sum(__expf(x - m));
            float lz = m + __logf(s);
            if (lane == 0) logZ[n] = lz;
            out[2 + n * SPW + lane] = x - lz;
        }
        if (n == 0 && tid == 1023) out[0] = 0.f;   // zero elbo accumulator
    } else {
        float pv = phi[(size_t)((Tm1 - 1) * Nn + n) * 1024 + lane * SPW + w];
        for (int t = Tm1 - 1; t >= 0; t--) {
            float pvn = (t > 0) ? phi[(size_t)((t - 1) * Nn + n) * 1024 + lane * SPW + w] : 0.f;
            if (tid < SPW) bn[(size_t)(t * Nn + n) * SPW + tid] = a_s[cur][tid];
            float x = pv + a_s[cur][lane];
            float m = warp_max(x);
            float s = warp_sum(__expf(x - m));
            if (lane == 0) a_s[cur ^ 1][w] = m + __logf(s);
            __syncthreads();
            cur ^= 1;
            pv = pvn;
        }
    }
}

// elbo + evidence fused
__global__ __launch_bounds__(1024) void elbo_k(
    const float* __restrict__ phi, const float* __restrict__ ap,
    const float* __restrict__ bn, const float* __restrict__ logZ,
    float* __restrict__ out)
{
    int e = blockIdx.x;
    int n = e % Nn;
    __shared__ float sap[SPW], sbn[SPW], ws[32];
    int tid = threadIdx.x;
    if (tid < SPW) { sap[tid] = ap[(size_t)e * SPW + tid]; sbn[tid] = bn[(size_t)e * SPW + tid]; }
    __syncthreads();
    int k = tid >> 5, j = tid & 31;
    float p = phi[(size_t)e * 1024 + tid];
    float term = __expf(sap[j] + p + sbn[k] - logZ[n]) * p;
    term = warp_sum(term);
    if (j == 0) ws[k] = term;
    __syncthreads();
    if (tid < 32) {
        float v = warp_sum(ws[tid]);
        if (tid == 0) atomicAdd(&out[0], v);
    }
    if (e == 0 && tid >= 64 && tid < 96) {      // evidence from a separate warp
        int lane2 = tid - 64;
        float lz = logZ[lane2];
        lz = warp_sum(lz);
        if (lane2 == 0) out[1] = lz;
    }
}

// ---------------- launcher ----------------
extern "C" void kernel_launch(void* const* d_in, const int* in_sizes, int n_in,
                              void* d_out, int out_size) {
    const float* start_emb = (const float*)d_in[0];
    const float* sw1  = (const float*)d_in[1];
    const float* sb1  = (const float*)d_in[2];
    const float* sw2  = (const float*)d_in[3];
    const float* sb2  = (const float*)d_in[4];
    const float* s_out_w = (const float*)d_in[5];
    const float* s_out_b = (const float*)d_in[6];
    const float* state_emb = (const float*)d_in[7];
    const float* tw1  = (const float*)d_in[8];
    const float* tb1  = (const float*)d_in[9];
    const float* tw2  = (const float*)d_in[10];
    const float* tb2  = (const float*)d_in[11];
    const float* nsp  = (const float*)d_in[12];
    const float* pre_emb = (const float*)d_in[13];
    const float* ew1  = (const float*)d_in[14];
    const float* eb1  = (const float*)d_in[15];
    const float* ew2  = (const float*)d_in[16];
    const float* eb2  = (const float*)d_in[17];
    const float* e_out_w = (const float*)d_in[18];
    const float* e_out_b = (const float*)d_in[19];
    const int* text = (const int*)d_in[20];
    const int* w2s  = (const int*)d_in[21];
    float* out = (float*)d_out;

    float* S = nullptr; int* RM = nullptr; uint32_t* U = nullptr;
    cudaGetSymbolAddress((void**)&S, g_scr);
    cudaGetSymbolAddress((void**)&RM, g_rowmax);
    cudaGetSymbolAddress((void**)&U, g_u);

    static bool inited = false;
    static cudaStream_t s1;
    static cudaEvent_t evB2, evEm;
    if (!inited) {
        cudaStreamCreateWithFlags(&s1, cudaStreamNonBlocking);
        cudaEventCreateWithFlags(&evB2, cudaEventDisableTiming);
        cudaEventCreateWithFlags(&evEm, cudaEventDisableTiming);
        inited = true;
    }

    // ---- prep: all input-only transforms in one launch ----
    Prep P;
    const float* em_[4] = { start_emb, state_emb, pre_emb, nsp };
    for (int j = 0; j < 3; j++) {
        P.psrc[j] = em_[j];
        P.phid[j] = U + UEMB + (size_t)j * 2 * SZ_MAT;
        P.plod[j] = U + UEMB + (size_t)j * 2 * SZ_MAT + SZ_MAT;
    }
    P.psrc[3] = nsp; P.phid[3] = U + UBH; P.plod[3] = U + UBL;
    const float* ws_[6] = { sw1, tw1, ew1, sw2, tw2, ew2 };
    for (int j = 0; j < 6; j++) {
        P.wsrc[j] = ws_[j];
        P.whid[j] = U + UWB + (size_t)j * 2 * WSZ;
        P.wlod[j] = U + UWB + (size_t)j * 2 * WSZ + WSZ;
    }
    P.ew = e_out_w; P.ewt = S + OFF_EWT;
    P.rm = RM; P.rsum = S + OFF_RSUM; P.slg = S + OFF_SLOG; P.soutb = s_out_b;
    prep_k<<<8512, 256>>>(P);

    // ---- MLPs ----
    const float* b1_[3] = { sb1, tb1, eb1 };
    PP3 m1;
    for (int j = 0; j < 3; j++)
        m1.p[j] = { U + UEMB + (size_t)j * 2 * SZ_MAT, U + UEMB + (size_t)j * 2 * SZ_MAT + SZ_MAT,
                    U + UWB + (size_t)j * 2 * WSZ, U + UWB + (size_t)j * 2 * WSZ + WSZ,
                    b1_[j], nullptr, nullptr, nullptr,
                    U + UHB + (size_t)j * 2 * SZ_MAT, U + UHB + (size_t)j * 2 * SZ_MAT + SZ_MAT };
    gemmp<1><<<dim3(Hh / 64, Cc / 128, 3), 256>>>(m1, nullptr, Hh);

    PP3 m2;
    m2.p[0] = { U + UHB + 0 * SZ_MAT, U + UHB + 1 * SZ_MAT,
                U + UWB + 3 * 2 * WSZ, U + UWB + 3 * 2 * WSZ + WSZ,
                sb2, start_emb, s_out_w, S + OFF_RS, nullptr, nullptr };
    m2.p[1] = { U + UHB + 2 * SZ_MAT, U + UHB + 3 * SZ_MAT,
                U + UWB + 4 * 2 * WSZ, U + UWB + 4 * 2 * WSZ + WSZ,
                tb2, state_emb, nullptr, nullptr, U + UAH, U + UAL };
    m2.p[2] = { U + UHB + 4 * SZ_MAT, U + UHB + 5 * SZ_MAT,
                U + UWB + 5 * 2 * WSZ, U + UWB + 5 * 2 * WSZ + WSZ,
                eb2, pre_emb, nullptr, S + OFF_RP, nullptr, nullptr };
    gemmp<2><<<dim3(Hh / 64, Cc / 128, 3), 256>>>(m2, S + OFF_SLOG, Hh);
    cudaEventRecord(evB2, 0);

    // ---- s1: emission chain (concurrent with trans GEMM) ----
    cudaStreamWaitEvent(s1, evB2, 0);
    emlog_k<<<Vv, 256, 0, s1>>>(S + OFF_RP, S + OFF_EWT, e_out_b, w2s, S + OFF_L, RM);
    emsum_k<<<Vv * SPW / 256, 256, 0, s1>>>(w2s, S + OFF_L, RM, S + OFF_RSUM);
    stlse_k<<<16, 256, 0, s1>>>(RM, S + OFF_RSUM, S + OFF_STLSE);
    cudaEventRecord(evEm, s1);

    // ---- main: trans GEMM + merged lse reductions ----
    gemm2_tc<<<dim3(Cc / 128, Cc / 128), 256>>>(U + UAH, U + UAL, U + UBH, U + UBL,
                                                S + OFF_TRANS, (float2*)(S + OFF_PART));
    merge_k<<<513, 256>>>((float2*)(S + OFF_PART), S + OFF_TLSE, S + OFF_SLOG, S + OFF_SLSE);

    // ---- join + tail ----
    cudaStreamWaitEvent(0, evEm, 0);
    phi_k<<<Nn * Tm1, 1024>>>(text, w2s, S + OFF_TRANS, S + OFF_TLSE,
                              S + OFF_L, S + OFF_STLSE, S + OFF_SLOG, S + OFF_SLSE,
                              S + OFF_PHI);
    scan_k<<<2 * Nn, 1024>>>(S + OFF_PHI, S + OFF_AP, S + OFF_BN, S + OFF_LOGZ, out);
    elbo_k<<<Tm1 * Nn, 1024>>>(S + OFF_PHI, S + OFF_AP, S + OFF_BN, S + OFF_LOGZ, out);
}

// round 8
// speedup vs baseline: 1.2195x; 1.1754x over previous
#include <cuda_runtime.h>
#include <cuda_fp16.h>
#include <math_constants.h>
#include <cstdint>
#include <cstddef>

static constexpr int Vv = 16000, Cc = 4096, Hh = 256, SPW = 32, Nn = 32, Tt = 128, Tm1 = 127;

// ---------------- scratch layout ----------------
constexpr size_t SZ_MAT   = (size_t)Cc * Hh;                  // 1,048,576
constexpr size_t OFF_RS   = 0;
constexpr size_t OFF_RP   = OFF_RS   + SZ_MAT;
constexpr size_t OFF_TRANS= OFF_RP   + SZ_MAT;                // 4096x4096
constexpr size_t OFF_TLSE = OFF_TRANS+ (size_t)Cc * Cc;
constexpr size_t OFF_SLOG = OFF_TLSE + Cc;
constexpr size_t OFF_SLSE = OFF_SLOG + Cc;
constexpr size_t OFF_EWT  = OFF_SLSE + 32;                    // V x H
constexpr size_t OFF_L    = OFF_EWT  + (size_t)Vv * Hh;       // V x SPW
constexpr size_t OFF_RSUM = OFF_L    + (size_t)Vv * SPW;
constexpr size_t OFF_STLSE= OFF_RSUM + Cc;
constexpr size_t OFF_PHI  = OFF_STLSE+ Cc;                    // Tm1*N*32*32
constexpr size_t OFF_AP   = OFF_PHI  + (size_t)Tm1 * Nn * SPW * SPW;
constexpr size_t OFF_BN   = OFF_AP   + (size_t)Tm1 * Nn * SPW;
constexpr size_t OFF_LOGZ = OFF_BN   + (size_t)Tm1 * Nn * SPW;
constexpr size_t OFF_PART = OFF_LOGZ + 64;                    // 4096 x 128 x (m,s)
constexpr size_t SCRATCH_TOTAL = OFF_PART + (size_t)Cc * 128 * 2;

__device__ float g_scr[SCRATCH_TOTAL];
__device__ int   g_rowmax[Cc];

// split buffers (u32 units; fp16 regions aliased as __half)
constexpr size_t WSZ = (size_t)Hh * Hh;                       // 65536
constexpr size_t UAH = 0, UAL = SZ_MAT;                       // RST fp16 hi/lo (half, aliased)
constexpr size_t UBH = 2 * SZ_MAT, UBL = 3 * SZ_MAT;          // nsp fp16 hi/lo (half, aliased)
constexpr size_t UEMB = 4 * SZ_MAT;                           // 3 x (hi,lo) embeddings (tf32)
constexpr size_t UHB  = 10 * SZ_MAT;                          // 3 x (hi,lo) H outputs (tf32)
constexpr size_t UWB  = 16 * SZ_MAT;                          // 6 x (hi,lo) weights (tf32)
__device__ uint32_t g_u[16 * SZ_MAT + 12 * WSZ];

// ---------------- helpers ----------------
__device__ __forceinline__ int ford(float f) {
    int i = __float_as_int(f);
    return i >= 0 ? i : (i ^ 0x7fffffff);
}
__device__ __forceinline__ float deord(int i) {
    return __int_as_float(i >= 0 ? i : (i ^ 0x7fffffff));
}
__device__ __forceinline__ void lse_acc(float& m, float& s, float v) {
    if (v > m) { s = s * __expf(m - v) + 1.f; m = v; }
    else       { s += __expf(v - m); }
}
__device__ __forceinline__ void lse_merge(float& m, float& s, float m2, float s2) {
    if (m2 > m) { s = s * __expf(m - m2) + s2; m = m2; }
    else        { s += s2 * __expf(m2 - m); }
}
__device__ __forceinline__ float warp_sum(float v) {
#pragma unroll
    for (int o = 16; o > 0; o >>= 1) v += __shfl_xor_sync(0xffffffffu, v, o);
    return v;
}
__device__ __forceinline__ float warp_max(float v) {
#pragma unroll
    for (int o = 16; o > 0; o >>= 1) v = fmaxf(v, __shfl_xor_sync(0xffffffffu, v, o));
    return v;
}

// ---------------- tf32 / fp16 utils ----------------
__device__ __forceinline__ uint32_t f2tf(float x) {
    uint32_t r;
    asm("cvt.rna.tf32.f32 %0, %1;" : "=r"(r) : "f"(x));
    return r;
}
__device__ __forceinline__ void tf_split(float x, uint32_t& hi, uint32_t& lo) {
    hi = f2tf(x);
    lo = f2tf(x - __uint_as_float(hi));
}
__device__ __forceinline__ void h_split(float x, __half& hi, __half& lo) {
    hi = __float2half_rn(x);
    lo = __float2half_rn(x - __half2float(hi));
}
__device__ __forceinline__ void mma_tf32(float4& d, const uint32_t* a, const uint32_t* b) {
    asm volatile(
        "mma.sync.aligned.m16n8k8.row.col.f32.tf32.tf32.f32 "
        "{%0,%1,%2,%3}, {%4,%5,%6,%7}, {%8,%9}, {%0,%1,%2,%3};"
        : "+f"(d.x), "+f"(d.y), "+f"(d.z), "+f"(d.w)
        : "r"(a[0]), "r"(a[1]), "r"(a[2]), "r"(a[3]), "r"(b[0]), "r"(b[1]));
}
__device__ __forceinline__ void mma_f16(float4& d, const uint32_t* a, const uint32_t* b) {
    asm volatile(
        "mma.sync.aligned.m16n8k16.row.col.f32.f16.f16.f32 "
        "{%0,%1,%2,%3}, {%4,%5,%6,%7}, {%8,%9}, {%0,%1,%2,%3};"
        : "+f"(d.x), "+f"(d.y), "+f"(d.z), "+f"(d.w)
        : "r"(a[0]), "r"(a[1]), "r"(a[2]), "r"(a[3]), "r"(b[0]), "r"(b[1]));
}
__device__ __forceinline__ void cpasync16(uint32_t dst, const void* src) {
    asm volatile("cp.async.cg.shared.global [%0], [%1], 16;" :: "r"(dst), "l"(src));
}
__device__ __forceinline__ void cp_commit() { asm volatile("cp.async.commit_group;"); }
template <int N> __device__ __forceinline__ void cp_wait() {
    asm volatile("cp.async.wait_group %0;" :: "n"(N));
}

// ---------------- unified prep kernel ----------------
// blocks [0,3072): tf32 presplit 3 embeddings; [3072,4096): fp16 presplit nsp;
// [4096,4480): wt transpose+split x6; [4480,8480): ewT transpose; [8480,8512): inits.
struct Prep {
    const float* psrc[4]; uint32_t* phid[4]; uint32_t* plod[4];
    const float* wsrc[6]; uint32_t* whid[6]; uint32_t* wlod[6];
    const float* ew; float* ewt;
    int* rm; float* rsum; float* slg; const float* soutb;
};
__global__ __launch_bounds__(256) void prep_k(Prep P) {
    __shared__ float t[32][33];
    int b = blockIdx.x, tid = threadIdx.x;
    if (b < 4096) {
        int mat = b >> 10;
        int i = (b & 1023) * 256 + tid;
        float4 v = ((const float4*)P.psrc[mat])[i];
        if (mat < 3) {
            uint4 h, l;
            tf_split(v.x, h.x, l.x); tf_split(v.y, h.y, l.y);
            tf_split(v.z, h.z, l.z); tf_split(v.w, h.w, l.w);
            ((uint4*)P.phid[mat])[i] = h; ((uint4*)P.plod[mat])[i] = l;
        } else {
            __half hx, lx, hy, ly, hz, lz, hw, lw;
            h_split(v.x, hx, lx); h_split(v.y, hy, ly);
            h_split(v.z, hz, lz); h_split(v.w, hw, lw);
            __half2* H = (__half2*)P.phid[3];
            __half2* L2 = (__half2*)P.plod[3];
            H[2 * i] = __halves2half2(hx, hy);  H[2 * i + 1] = __halves2half2(hz, hw);
            L2[2 * i] = __halves2half2(lx, ly); L2[2 * i + 1] = __halves2half2(lz, lw);
        }
    } else if (b < 4480) {
        int idx = b - 4096;
        int mat = idx >> 6, p = idx & 63;
        int bx = (p & 7) * 32, by = (p >> 3) * 32;
        int x = tid & 31, y = tid >> 5;
        const float* w = P.wsrc[mat];
#pragma unroll
        for (int i = 0; i < 32; i += 8)
            t[y + i][x] = w[(size_t)(by + y + i) * Hh + bx + x];
        __syncthreads();
#pragma unroll
        for (int i = 0; i < 32; i += 8) {
            float v = t[x][y + i];
            uint32_t h, l;
            tf_split(v, h, l);
            P.whid[mat][(size_t)(bx + y + i) * Hh + by + x] = h;
            P.wlod[mat][(size_t)(bx + y + i) * Hh + by + x] = l;
        }
    } else if (b < 8480) {
        int p = b - 4480;
        int bx = (p % 500) * 32, by = (p / 500) * 32;
        int x = tid & 31, y = tid >> 5;
#pragma unroll
        for (int i = 0; i < 32; i += 8)
            t[y + i][x] = P.ew[(size_t)(by + y + i) * Vv + bx + x];
        __syncthreads();
#pragma unroll
        for (int i = 0; i < 32; i += 8)
            P.ewt[(size_t)(bx + y + i) * Hh + by + x] = t[x][y + i];
    } else {
        int i = (b - 8480) * 256 + tid;
        if (i < Cc) { P.rm[i] = (int)0x80000000; P.rsum[i] = 0.f; }
        else        { P.slg[i - Cc] = P.soutb[0]; }
    }
}

// ---------------- MLP GEMM: 128x64 tile pipelined pre-split tf32 -------
struct PP { const uint32_t *Ah, *Al, *Bh, *Bl; const float *bias, *R, *sw;
            float *C; uint32_t *Ch, *Cl; __half *Hh2, *Hl2; };
struct PP3 { PP p[3]; };

template <int EPI>
__global__ __launch_bounds__(256) void gemmp(PP3 bt, float* __restrict__ slogp, int N) {
    constexpr int K = 256, NIT = K / 8, BUF = 4608;
    __shared__ uint32_t smem[2 * BUF];
    const PP pp = bt.p[blockIdx.z];
    int tid = threadIdx.x, wid = tid >> 5, lane = tid & 31;
    int gid = lane >> 2, tg = lane & 3;
    int bm = blockIdx.y * 128, bn = blockIdx.x * 64;
    int warp_m = (wid & 3) * 32, warp_n = (wid >> 2) * 32;

    const uint32_t* gsrc[3]; uint32_t doff[3];
#pragma unroll
    for (int i = 0; i < 3; i++) {
        int ch = tid + i * 256;
        if (ch < 512) {
            int mat = ch >> 8, r = (ch >> 1) & 127, c4 = (ch & 1) * 4;
            gsrc[i] = (mat ? pp.Al : pp.Ah) + (size_t)(bm + r) * K + c4;
            doff[i] = mat * 1536 + r * 12 + c4;
        } else {
            int idx = ch - 512;
            int mat = idx >> 7, r = (idx >> 1) & 63, c4 = (idx & 1) * 4;
            gsrc[i] = (mat ? pp.Bl : pp.Bh) + (size_t)(bn + r) * K + c4;
            doff[i] = 3072 + mat * 768 + r * 12 + c4;
        }
    }
    uint32_t sbase = (uint32_t)__cvta_generic_to_shared(smem);

    float4 acc[2][4];
#pragma unroll
    for (int i = 0; i < 2; i++)
#pragma unroll
        for (int j = 0; j < 4; j++) acc[i][j] = make_float4(0.f, 0.f, 0.f, 0.f);

    {
#pragma unroll
        for (int i = 0; i < 3; i++) cpasync16(sbase + doff[i] * 4, gsrc[i]);
        cp_commit();
    }
    for (int it = 0; it < NIT; it++) {
        if (it + 1 < NIT) {
            uint32_t b = sbase + ((it + 1) & 1) * (BUF * 4);
#pragma unroll
            for (int i = 0; i < 3; i++) cpasync16(b + doff[i] * 4, gsrc[i] + (it + 1) * 8);
            cp_commit();
            cp_wait<1>();
        } else {
            cp_wait<0>();
        }
        __syncthreads();
        const uint32_t* buf = smem + (it & 1) * BUF;
        uint32_t ah[2][4], al[2][4], bh[4][2], bl[4][2];
#pragma unroll
        for (int mt = 0; mt < 2; mt++) {
            int rb = warp_m + mt * 16 + gid;
            ah[mt][0] = buf[rb * 12 + tg];           al[mt][0] = buf[1536 + rb * 12 + tg];
            ah[mt][1] = buf[(rb + 8) * 12 + tg];     al[mt][1] = buf[1536 + (rb + 8) * 12 + tg];
            ah[mt][2] = buf[rb * 12 + tg + 4];       al[mt][2] = buf[1536 + rb * 12 + tg + 4];
            ah[mt][3] = buf[(rb + 8) * 12 + tg + 4]; al[mt][3] = buf[1536 + (rb + 8) * 12 + tg + 4];
        }
#pragma unroll
        for (int nt = 0; nt < 4; nt++) {
            int cb = warp_n + nt * 8 + gid;
            bh[nt][0] = buf[3072 + cb * 12 + tg];     bl[nt][0] = buf[3840 + cb * 12 + tg];
            bh[nt][1] = buf[3072 + cb * 12 + tg + 4]; bl[nt][1] = buf[3840 + cb * 12 + tg + 4];
        }
#pragma unroll
        for (int mt = 0; mt < 2; mt++)
#pragma unroll
            for (int nt = 0; nt < 4; nt++) {
                mma_tf32(acc[mt][nt], ah[mt], bh[nt]);
                mma_tf32(acc[mt][nt], al[mt], bh[nt]);
                mma_tf32(acc[mt][nt], ah[mt], bl[nt]);
            }
        __syncthreads();
    }

#pragma unroll
    for (int mt = 0; mt < 2; mt++) {
        int row0 = bm + warp_m + mt * 16 + gid;
        float pr0 = 0.f, pr8 = 0.f;
#pragma unroll
        for (int nt = 0; nt < 4; nt++) {
            int col = bn + warp_n + nt * 8 + 2 * tg;
            float4 v = acc[mt][nt];
            float b0 = pp.bias[col], b1 = pp.bias[col + 1];
            v.x = fmaxf(v.x + b0, 0.f); v.y = fmaxf(v.y + b1, 0.f);
            v.z = fmaxf(v.z + b0, 0.f); v.w = fmaxf(v.w + b1, 0.f);
            if (EPI == 2) {
                float2 r0 = *(const float2*)&pp.R[(size_t)row0 * N + col];
                float2 r1 = *(const float2*)&pp.R[(size_t)(row0 + 8) * N + col];
                v.x += r0.x; v.y += r0.y; v.z += r1.x; v.w += r1.y;
                if (pp.sw) {
                    float w0 = pp.sw[col], w1 = pp.sw[col + 1];
                    pr0 += v.x * w0 + v.y * w1;
                    pr8 += v.z * w0 + v.w * w1;
                }
            }
            if (pp.C) {
                *(float2*)&pp.C[(size_t)row0 * N + col] = make_float2(v.x, v.y);
                *(float2*)&pp.C[(size_t)(row0 + 8) * N + col] = make_float2(v.z, v.w);
            }
            if (pp.Ch) {
                uint32_t hx, lx, hy, ly, hz, lz, hw, lw;
                tf_split(v.x, hx, lx); tf_split(v.y, hy, ly);
                tf_split(v.z, hz, lz); tf_split(v.w, hw, lw);
                *(uint2*)&pp.Ch[(size_t)row0 * N + col] = make_uint2(hx, hy);
                *(uint2*)&pp.Cl[(size_t)row0 * N + col] = make_uint2(lx, ly);
                *(uint2*)&pp.Ch[(size_t)(row0 + 8) * N + col] = make_uint2(hz, hw);
                *(uint2*)&pp.Cl[(size_t)(row0 + 8) * N + col] = make_uint2(lz, lw);
            }
            if (EPI == 2 && pp.Hh2) {
                __half hx, lx, hy, ly, hz, lz, hw, lw;
                h_split(v.x, hx, lx); h_split(v.y, hy, ly);
                h_split(v.z, hz, lz); h_split(v.w, hw, lw);
                *(__half2*)&pp.Hh2[(size_t)row0 * N + col] = __halves2half2(hx, hy);
                *(__half2*)&pp.Hl2[(size_t)row0 * N + col] = __halves2half2(lx, ly);
                *(__half2*)&pp.Hh2[(size_t)(row0 + 8) * N + col] = __halves2half2(hz, hw);
                *(__half2*)&pp.Hl2[(size_t)(row0 + 8) * N + col] = __halves2half2(lz, lw);
            }
        }
        if (EPI == 2 && pp.sw) {
            pr0 += __shfl_xor_sync(0xffffffffu, pr0, 1);
            pr0 += __shfl_xor_sync(0xffffffffu, pr0, 2);
            pr8 += __shfl_xor_sync(0xffffffffu, pr8, 1);
            pr8 += __shfl_xor_sync(0xffffffffu, pr8, 2);
            if (tg == 0) {
                atomicAdd(&slogp[row0], pr0);
                atomicAdd(&slogp[row0 + 8], pr8);
            }
        }
    }
}

// ---------------- trans GEMM: fp16 3-split, m16n8k16, 128x128 tile, fused lse --
// stage layout (bytes): mat*6144 + row*48 + chunk*16; mats: Ah, Al, Bh, Bl.
__global__ __launch_bounds__(256) void gemm2_h(
    const __half* __restrict__ Ahg, const __half* __restrict__ Alg,
    const __half* __restrict__ Bhg, const __half* __restrict__ Blg,
    float* __restrict__ C, float2* __restrict__ part)
{
    constexpr int NIT = 16, BUFB = 24576;        // 24KB per stage
    __shared__ uint32_t smem[2 * BUFB / 4];      // 48KB
    int tid = threadIdx.x, wid = tid >> 5, lane = tid & 31;
    int gid = lane >> 2, tg = lane & 3;
    int bm = blockIdx.y * 128, bn = blockIdx.x * 128;
    int warp_m = (wid & 1) * 64, warp_n = (wid >> 1) * 32;

    const __half* gsrc[4]; uint32_t doff[4];
#pragma unroll
    for (int i = 0; i < 4; i++) {
        int ch = tid + i * 256;                  // 0..1023
        int mat = ch >> 8;                       // 0 Ah,1 Al,2 Bh,3 Bl
        int idx = ch & 255, r = idx >> 1, c = idx & 1;
        const __half* g = (mat == 0) ? Ahg : (mat == 1) ? Alg : (mat == 2) ? Bhg : Blg;
        int row = ((mat < 2) ? bm : bn) + r;
        gsrc[i] = g + (size_t)row * 256 + c * 8;
        doff[i] = mat * 6144 + r * 48 + c * 16;  // bytes
    }
    uint32_t sbase = (uint32_t)__cvta_generic_to_shared(smem);

    float4 acc[4][4];
#pragma unroll
    for (int i = 0; i < 4; i++)
#pragma unroll
        for (int j = 0; j < 4; j++) acc[i][j] = make_float4(0.f, 0.f, 0.f, 0.f);

    {
#pragma unroll
        for (int i = 0; i < 4; i++) cpasync16(sbase + doff[i], gsrc[i]);
        cp_commit();
    }
    for (int it = 0; it < NIT; it++) {
        if (it + 1 < NIT) {
            uint32_t b = sbase + ((it + 1) & 1) * BUFB;
#pragma unroll
            for (int i = 0; i < 4; i++) cpasync16(b + doff[i], gsrc[i] + (it + 1) * 16);
            cp_commit();
            cp_wait<1>();
        } else {
            cp_wait<0>();
        }
        __syncthreads();
        const uint32_t* buf = smem + (it & 1) * (BUFB / 4);   // u32 index
        // u32 strides: row stride 12, mat stride 1536
        uint32_t ah[4][4], al[4][4], bh[4][2], bl[4][2];
#pragma unroll
        for (int mt = 0; mt < 4; mt++) {
            int rb = warp_m + mt * 16 + gid;
            ah[mt][0] = buf[rb * 12 + tg];           al[mt][0] = buf[1536 + rb * 12 + tg];
            ah[mt][1] = buf[(rb + 8) * 12 + tg];     al[mt][1] = buf[1536 + (rb + 8) * 12 + tg];
            ah[mt][2] = buf[rb * 12 + tg + 4];       al[mt][2] = buf[1536 + rb * 12 + tg + 4];
            ah[mt][3] = buf[(rb + 8) * 12 + tg + 4]; al[mt][3] = buf[1536 + (rb + 8) * 12 + tg + 4];
        }
#pragma unroll
        for (int nt = 0; nt < 4; nt++) {
            int cb = warp_n + nt * 8 + gid;
            bh[nt][0] = buf[3072 + cb * 12 + tg];     bl[nt][0] = buf[4608 + cb * 12 + tg];
            bh[nt][1] = buf[3072 + cb * 12 + tg + 4]; bl[nt][1] = buf[4608 + cb * 12 + tg + 4];
        }
#pragma unroll
        for (int mt = 0; mt < 4; mt++)
#pragma unroll
            for (int nt = 0; nt < 4; nt++) {
                mma_f16(acc[mt][nt], ah[mt], bh[nt]);
                mma_f16(acc[mt][nt], al[mt], bh[nt]);
                mma_f16(acc[mt][nt], ah[mt], bl[nt]);
            }
        __syncthreads();
    }

    int chunk = blockIdx.x * 4 + (wid >> 1);
#pragma unroll
    for (int mt = 0; mt < 4; mt++) {
        int row0 = bm + warp_m + mt * 16 + gid;
        float m0 = -CUDART_INF_F, s0 = 0.f, m8 = -CUDART_INF_F, s8 = 0.f;
#pragma unroll
        for (int nt = 0; nt < 4; nt++) {
            int col = bn + warp_n + nt * 8 + 2 * tg;
            float4 v = acc[mt][nt];
            *(float2*)&C[(size_t)row0 * Cc + col] = make_float2(v.x, v.y);
            *(float2*)&C[(size_t)(row0 + 8) * Cc + col] = make_float2(v.z, v.w);
            lse_acc(m0, s0, v.x); lse_acc(m0, s0, v.y);
            lse_acc(m8, s8, v.z); lse_acc(m8, s8, v.w);
        }
#pragma unroll
        for (int o = 1; o <= 2; o <<= 1) {
            float m2 = __shfl_xor_sync(0xffffffffu, m0, o);
            float s2 = __shfl_xor_sync(0xffffffffu, s0, o);
            lse_merge(m0, s0, m2, s2);
            m2 = __shfl_xor_sync(0xffffffffu, m8, o);
            s2 = __shfl_xor_sync(0xffffffffu, s8, o);
            lse_merge(m8, s8, m2, s2);
        }
        if (tg == 0) {
            part[(size_t)row0 * 128 + chunk] = make_float2(m0, s0);
            part[(size_t)(row0 + 8) * 128 + chunk] = make_float2(m8, s8);
        }
    }
}

// merge: blocks [0,512) tlse rows; block 512 computes slse from slog
__global__ void merge_k(const float2* __restrict__ part, float* __restrict__ tlse,
                        const float* __restrict__ slog, float* __restrict__ slse) {
    int tid = threadIdx.x;
    if (blockIdx.x < 512) {
        int row = blockIdx.x * 8 + (tid >> 5);
        int lane = tid & 31;
        float m = -CUDART_INF_F, s = 0.f;
#pragma unroll
        for (int i = 0; i < 4; i++) {
            float2 p = part[(size_t)row * 128 + lane + 32 * i];
            lse_merge(m, s, p.x, p.y);
        }
#pragma unroll
        for (int o = 16; o > 0; o >>= 1) {
            float m2 = __shfl_xor_sync(0xffffffffu, m, o);
            float s2 = __shfl_xor_sync(0xffffffffu, s, o);
            lse_merge(m, s, m2, s2);
        }
        if (lane == 0) tlse[row] = m + __logf(s);
    } else {
        float m = -CUDART_INF_F, s = 0.f;
        for (int i = tid; i < Cc; i += 256) lse_acc(m, s, slog[i]);
#pragma unroll
        for (int o = 16; o > 0; o >>= 1) {
            float m2 = __shfl_xor_sync(0xffffffffu, m, o);
            float s2 = __shfl_xor_sync(0xffffffffu, s, o);
            lse_merge(m, s, m2, s2);
        }
        __shared__ float sm[8], ss[8];
        int w = tid >> 5, lane = tid & 31;
        if (lane == 0) { sm[w] = m; ss[w] = s; }
        __syncthreads();
        if (tid == 0) {
            float M = sm[0], S = ss[0];
            for (int i = 1; i < 8; i++) lse_merge(M, S, sm[i], ss[i]);
            slse[0] = M + __logf(S);
        }
    }
}

// sparse emission logits
__global__ __launch_bounds__(256) void emlog_k(
    const float* __restrict__ pre, const float* __restrict__ ewT,
    const float* __restrict__ eb, const int* __restrict__ w2s,
    float* __restrict__ L, int* __restrict__ rowmax)
{
    int v = blockIdx.x;
    __shared__ float4 ecol4[64];
    __shared__ int st[SPW];
    int tid = threadIdx.x;
    if (tid < 64) ecol4[tid] = ((const float4*)(ewT + (size_t)v * Hh))[tid];
    if (tid >= 224) st[tid - 224] = w2s[v * SPW + (tid - 224)];
    __syncthreads();
    int w = tid >> 5, lane = tid & 31;
    float4 e0 = ecol4[lane], e1 = ecol4[lane + 32];
    float bv = eb[v];
#pragma unroll
    for (int q = 0; q < 4; q++) {
        int jj = w + q * 8;
        int c = st[jj];
        const float4* pr = (const float4*)(pre + (size_t)c * Hh);
        float4 p0 = pr[lane], p1 = pr[lane + 32];
        float p = p0.x * e0.x + p0.y * e0.y + p0.z * e0.z + p0.w * e0.w
                + p1.x * e1.x + p1.y * e1.y + p1.z * e1.z + p1.w * e1.w;
        p = warp_sum(p);
        if (lane == 0) {
            float val = p + bv;
            L[v * SPW + jj] = val;
            atomicMax(&rowmax[c], ford(val));
        }
    }
}

__global__ void emsum_k(const int* __restrict__ w2s, const float* __restrict__ L,
                        const int* __restrict__ rm, float* __restrict__ rsum) {
    int gid = blockIdx.x * 256 + threadIdx.x;
    int v = gid >> 5, j = gid & 31;
    int c = w2s[v * SPW + j];
    for (int jp = 0; jp < j; jp++)
        if (w2s[v * SPW + jp] == c) return;
    atomicAdd(&rsum[c], __expf(L[gid] - deord(rm[c])));
}

__global__ void stlse_k(const int* __restrict__ rm, const float* __restrict__ rsum,
                        float* __restrict__ stlse) {
    int i = blockIdx.x * 256 + threadIdx.x;
    if (i < Cc) stlse[i] = deord(rm[i]) + __logf(rsum[i]);
}

// phi with obs/init fused; warp-per-row gather + smem transpose, coalesced write
__global__ __launch_bounds__(1024) void phi_k(
    const int* __restrict__ text, const int* __restrict__ w2s,
    const float* __restrict__ trans, const float* __restrict__ tlse,
    const float* __restrict__ L, const float* __restrict__ stlse,
    const float* __restrict__ slog, const float* __restrict__ slse,
    float* __restrict__ phi)
{
    int b = blockIdx.x;
    int n = b / Tm1, t = b % Tm1;
    __shared__ int c0[SPW], c1[SPW];
    __shared__ float ob1[SPW], iob[SPW], tl0[SPW];
    __shared__ float tile[SPW * 33];
    int tid = threadIdx.x;
    if (tid < SPW) {
        int v0 = text[n * Tt + t], v1 = text[n * Tt + t + 1];
        int cc0 = w2s[v0 * SPW + tid], cc1 = w2s[v1 * SPW + tid];
        c0[tid] = cc0; c1[tid] = cc1;
        tl0[tid] = tlse[cc0];
        ob1[tid] = L[v1 * SPW + tid] - stlse[cc1];
        iob[tid] = (t == 0)
            ? (slog[cc0] - slse[0] + L[v0 * SPW + tid] - stlse[cc0]) : 0.f;
    }
    __syncthreads();
    int jw = tid >> 5, kl = tid & 31;
    float val = __ldg(&trans[(size_t)c0[jw] * Cc + c1[kl]]) - tl0[jw] + ob1[kl] + iob[jw];
    tile[jw * 33 + kl] = val;
    __syncthreads();
    int kw = tid >> 5, jl = tid & 31;
    phi[(size_t)(t * Nn + n) * 1024 + kw * SPW + jl] = tile[jl * 33 + kw];
}

// forward (blocks 0..31) / backward (32..63) scans; 1 barrier per step
__global__ __launch_bounds__(1024) void scan_k(
    const float* __restrict__ phi, float* __restrict__ ap, float* __restrict__ bn,
    float* __restrict__ logZ, float* __restrict__ out)
{
    __shared__ float a_s[2][SPW];
    int tid = threadIdx.x, w = tid >> 5, lane = tid & 31;
    bool bwd = blockIdx.x >= Nn;
    int n = bwd ? (int)blockIdx.x - Nn : (int)blockIdx.x;
    if (tid < SPW) a_s[0][tid] = 0.f;
    __syncthreads();
    int cur = 0;
    if (!bwd) {
        float pv = phi[(size_t)n * 1024 + tid];
        for (int t = 0; t < Tm1; t++) {
            float pvn = (t + 1 < Tm1) ? phi[(size_t)((t + 1) * Nn + n) * 1024 + tid] : 0.f;
            if (tid < SPW) ap[(size_t)(t * Nn + n) * SPW + tid] = a_s[cur][tid];
            float x = pv + a_s[cur][lane];
            float m = warp_max(x);
            float s = warp_sum(__expf(x - m));
            if (lane == 0) a_s[cur ^ 1][w] = m + __logf(s);
            __syncthreads();
            cur ^= 1;
            pv = pvn;
        }
        if (w == 0) {
            float x = a_s[cur][lane];
            float m = warp_max(x);
            float s = warp_sum(__expf(x - m));
            float lz = m + __logf(s);
            if (lane == 0) logZ[n] = lz;
            out[2 + n * SPW + lane] = x - lz;
        }
        if (n == 0 && tid == 1023) out[0] = 0.f;
    } else {
        float pv = phi[(size_t)((Tm1 - 1) * Nn + n) * 1024 + lane * SPW + w];
        for (int t = Tm1 - 1; t >= 0; t--) {
            float pvn = (t > 0) ? phi[(size_t)((t - 1) * Nn + n) * 1024 + lane * SPW + w] : 0.f;
            if (tid < SPW) bn[(size_t)(t * Nn + n) * SPW + tid] = a_s[cur][tid];
            float x = pv + a_s[cur][lane];
            float m = warp_max(x);
            float s = warp_sum(__expf(x - m));
            if (lane == 0) a_s[cur ^ 1][w] = m + __logf(s);
            __syncthreads();
            cur ^= 1;
            pv = pvn;
        }
    }
}

// elbo + evidence fused
__global__ __launch_bounds__(1024) void elbo_k(
    const float* __restrict__ phi, const float* __restrict__ ap,
    const float* __restrict__ bn, const float* __restrict__ logZ,
    float* __restrict__ out)
{
    int e = blockIdx.x;
    int n = e % Nn;
    __shared__ float sap[SPW], sbn[SPW], ws[32];
    int tid = threadIdx.x;
    if (tid < SPW) { sap[tid] = ap[(size_t)e * SPW + tid]; sbn[tid] = bn[(size_t)e * SPW + tid]; }
    __syncthreads();
    int k = tid >> 5, j = tid & 31;
    float p = phi[(size_t)e * 1024 + tid];
    float term = __expf(sap[j] + p + sbn[k] - logZ[n]) * p;
    term = warp_sum(term);
    if (j == 0) ws[k] = term;
    __syncthreads();
    if (tid < 32) {
        float v = warp_sum(ws[tid]);
        if (tid == 0) atomicAdd(&out[0], v);
    }
    if (e == 0 && tid >= 64 && tid < 96) {
        int lane2 = tid - 64;
        float lz = logZ[lane2];
        lz = warp_sum(lz);
        if (lane2 == 0) out[1] = lz;
    }
}

// ---------------- launcher ----------------
extern "C" void kernel_launch(void* const* d_in, const int* in_sizes, int n_in,
                              void* d_out, int out_size) {
    const float* start_emb = (const float*)d_in[0];
    const float* sw1  = (const float*)d_in[1];
    const float* sb1  = (const float*)d_in[2];
    const float* sw2  = (const float*)d_in[3];
    const float* sb2  = (const float*)d_in[4];
    const float* s_out_w = (const float*)d_in[5];
    const float* s_out_b = (const float*)d_in[6];
    const float* state_emb = (const float*)d_in[7];
    const float* tw1  = (const float*)d_in[8];
    const float* tb1  = (const float*)d_in[9];
    const float* tw2  = (const float*)d_in[10];
    const float* tb2  = (const float*)d_in[11];
    const float* nsp  = (const float*)d_in[12];
    const float* pre_emb = (const float*)d_in[13];
    const float* ew1  = (const float*)d_in[14];
    const float* eb1  = (const float*)d_in[15];
    const float* ew2  = (const float*)d_in[16];
    const float* eb2  = (const float*)d_in[17];
    const float* e_out_w = (const float*)d_in[18];
    const float* e_out_b = (const float*)d_in[19];
    const int* text = (const int*)d_in[20];
    const int* w2s  = (const int*)d_in[21];
    float* out = (float*)d_out;

    float* S = nullptr; int* RM = nullptr; uint32_t* U = nullptr;
    cudaGetSymbolAddress((void**)&S, g_scr);
    cudaGetSymbolAddress((void**)&RM, g_rowmax);
    cudaGetSymbolAddress((void**)&U, g_u);

    static bool inited = false;
    static cudaStream_t s1;
    static cudaEvent_t evB2, evEm;
    if (!inited) {
        cudaStreamCreateWithFlags(&s1, cudaStreamNonBlocking);
        cudaEventCreateWithFlags(&evB2, cudaEventDisableTiming);
        cudaEventCreateWithFlags(&evEm, cudaEventDisableTiming);
        inited = true;
    }

    // ---- prep ----
    Prep P;
    const float* em_[4] = { start_emb, state_emb, pre_emb, nsp };
    for (int j = 0; j < 3; j++) {
        P.psrc[j] = em_[j];
        P.phid[j] = U + UEMB + (size_t)j * 2 * SZ_MAT;
        P.plod[j] = U + UEMB + (size_t)j * 2 * SZ_MAT + SZ_MAT;
    }
    P.psrc[3] = nsp; P.phid[3] = U + UBH; P.plod[3] = U + UBL;
    const float* ws_[6] = { sw1, tw1, ew1, sw2, tw2, ew2 };
    for (int j = 0; j < 6; j++) {
        P.wsrc[j] = ws_[j];
        P.whid[j] = U + UWB + (size_t)j * 2 * WSZ;
        P.wlod[j] = U + UWB + (size_t)j * 2 * WSZ + WSZ;
    }
    P.ew = e_out_w; P.ewt = S + OFF_EWT;
    P.rm = RM; P.rsum = S + OFF_RSUM; P.slg = S + OFF_SLOG; P.soutb = s_out_b;
    prep_k<<<8512, 256>>>(P);

    // ---- MLPs ----
    const float* b1_[3] = { sb1, tb1, eb1 };
    PP3 m1;
    for (int j = 0; j < 3; j++) {
        PP& q = m1.p[j];
        q.Ah = U + UEMB + (size_t)j * 2 * SZ_MAT;
        q.Al = U + UEMB + (size_t)j * 2 * SZ_MAT + SZ_MAT;
        q.Bh = U + UWB + (size_t)j * 2 * WSZ;
        q.Bl = U + UWB + (size_t)j * 2 * WSZ + WSZ;
        q.bias = b1_[j]; q.R = nullptr; q.sw = nullptr; q.C = nullptr;
        q.Ch = U + UHB + (size_t)j * 2 * SZ_MAT;
        q.Cl = U + UHB + (size_t)j * 2 * SZ_MAT + SZ_MAT;
        q.Hh2 = nullptr; q.Hl2 = nullptr;
    }
    gemmp<1><<<dim3(Hh / 64, Cc / 128, 3), 256>>>(m1, nullptr, Hh);

    PP3 m2;
    {
        PP& q = m2.p[0];
        q.Ah = U + UHB + 0 * SZ_MAT; q.Al = U + UHB + 1 * SZ_MAT;
        q.Bh = U + UWB + 3 * 2 * WSZ; q.Bl = U + UWB + 3 * 2 * WSZ + WSZ;
        q.bias = sb2; q.R = start_emb; q.sw = s_out_w;
        q.C = S + OFF_RS; q.Ch = nullptr; q.Cl = nullptr; q.Hh2 = nullptr; q.Hl2 = nullptr;
    }
    {
        PP& q = m2.p[1];
        q.Ah = U + UHB + 2 * SZ_MAT; q.Al = U + UHB + 3 * SZ_MAT;
        q.Bh = U + UWB + 4 * 2 * WSZ; q.Bl = U + UWB + 4 * 2 * WSZ + WSZ;
        q.bias = tb2; q.R = state_emb; q.sw = nullptr;
        q.C = nullptr; q.Ch = nullptr; q.Cl = nullptr;
        q.Hh2 = (__half*)(U + UAH); q.Hl2 = (__half*)(U + UAL);
    }
    {
        PP& q = m2.p[2];
        q.Ah = U + UHB + 4 * SZ_MAT; q.Al = U + UHB + 5 * SZ_MAT;
        q.Bh = U + UWB + 5 * 2 * WSZ; q.Bl = U + UWB + 5 * 2 * WSZ + WSZ;
        q.bias = eb2; q.R = pre_emb; q.sw = nullptr;
        q.C = S + OFF_RP; q.Ch = nullptr; q.Cl = nullptr; q.Hh2 = nullptr; q.Hl2 = nullptr;
    }
    gemmp<2><<<dim3(Hh / 64, Cc / 128, 3), 256>>>(m2, S + OFF_SLOG, Hh);
    cudaEventRecord(evB2, 0);

    // ---- s1: emission chain (concurrent with trans GEMM) ----
    cudaStreamWaitEvent(s1, evB2, 0);
    emlog_k<<<Vv, 256, 0, s1>>>(S + OFF_RP, S + OFF_EWT, e_out_b, w2s, S + OFF_L, RM);
    emsum_k<<<Vv * SPW / 256, 256, 0, s1>>>(w2s, S + OFF_L, RM, S + OFF_RSUM);
    stlse_k<<<16, 256, 0, s1>>>(RM, S + OFF_RSUM, S + OFF_STLSE);
    cudaEventRecord(evEm, s1);

    // ---- main: fp16 trans GEMM + merged lse reductions ----
    gemm2_h<<<dim3(Cc / 128, Cc / 128), 256>>>(
        (const __half*)(U + UAH), (const __half*)(U + UAL),
        (const __half*)(U + UBH), (const __half*)(U + UBL),
        S + OFF_TRANS, (float2*)(S + OFF_PART));
    merge_k<<<513, 256>>>((float2*)(S + OFF_PART), S + OFF_TLSE, S + OFF_SLOG, S + OFF_SLSE);

    // ---- join + tail ----
    cudaStreamWaitEvent(0, evEm, 0);
    phi_k<<<Nn * Tm1, 1024>>>(text, w2s, S + OFF_TRANS, S + OFF_TLSE,
                              S + OFF_L, S + OFF_STLSE, S + OFF_SLOG, S + OFF_SLSE,
                              S + OFF_PHI);
    scan_k<<<2 * Nn, 1024>>>(S + OFF_PHI, S + OFF_AP, S + OFF_BN, S + OFF_LOGZ, out);
    elbo_k<<<Tm1 * Nn, 1024>>>(S + OFF_PHI, S + OFF_AP, S + OFF_BN, S + OFF_LOGZ, out);
}

// round 9
// speedup vs baseline: 1.3603x; 1.1154x over previous
#include <cuda_runtime.h>
#include <cuda_fp16.h>
#include <math_constants.h>
#include <cstdint>
#include <cstddef>

static constexpr int Vv = 16000, Cc = 4096, Hh = 256, SPW = 32, Nn = 32, Tt = 128, Tm1 = 127;

// ---------------- scratch layout ----------------
constexpr size_t SZ_MAT   = (size_t)Cc * Hh;                  // 1,048,576
constexpr size_t OFF_RS   = 0;
constexpr size_t OFF_RP   = OFF_RS   + SZ_MAT;
constexpr size_t OFF_TRANS= OFF_RP   + SZ_MAT;                // 4096x4096
constexpr size_t OFF_TLSE = OFF_TRANS+ (size_t)Cc * Cc;
constexpr size_t OFF_SLOG = OFF_TLSE + Cc;
constexpr size_t OFF_SLSE = OFF_SLOG + Cc;
constexpr size_t OFF_EWT  = OFF_SLSE + 32;                    // V x H
constexpr size_t OFF_L    = OFF_EWT  + (size_t)Vv * Hh;       // V x SPW
constexpr size_t OFF_RSUM = OFF_L    + (size_t)Vv * SPW;
constexpr size_t OFF_STLSE= OFF_RSUM + Cc;
constexpr size_t OFF_PHI  = OFF_STLSE+ Cc;                    // Tm1*N*32*32
constexpr size_t OFF_AP   = OFF_PHI  + (size_t)Tm1 * Nn * SPW * SPW;
constexpr size_t OFF_BN   = OFF_AP   + (size_t)Tm1 * Nn * SPW;
constexpr size_t OFF_LOGZ = OFF_BN   + (size_t)Tm1 * Nn * SPW;
constexpr size_t OFF_PART = OFF_LOGZ + 64;                    // 4096 x 128 x (m,s)
constexpr size_t SCRATCH_TOTAL = OFF_PART + (size_t)Cc * 128 * 2;

__device__ float g_scr[SCRATCH_TOTAL];
__device__ int   g_rowmax[Cc];

// fp16 split buffers (u32 units; aliased as __half)
constexpr size_t WSZ = (size_t)Hh * Hh;                       // 65536
constexpr size_t HS  = SZ_MAT / 2;                            // u32 per half-matrix (4096x256 fp16)
constexpr size_t HWS = WSZ / 2;                               // u32 per half weight (256x256 fp16)
constexpr size_t RSTh = 0, RSTl = HS;                         // RST fp16 hi/lo
constexpr size_t NSPh = 2 * HS, NSPl = 3 * HS;                // nsp fp16 hi/lo
constexpr size_t HEMB = 4 * HS;                               // 3 x (hi,lo) embeddings
constexpr size_t HOUT = 10 * HS;                              // 3 x (hi,lo) H outputs
constexpr size_t HWB  = 16 * HS;                              // 6 x (hi,lo) weights (transposed)
__device__ uint32_t g_u[16 * HS + 12 * HWS];

// ---------------- helpers ----------------
__device__ __forceinline__ int ford(float f) {
    int i = __float_as_int(f);
    return i >= 0 ? i : (i ^ 0x7fffffff);
}
__device__ __forceinline__ float deord(int i) {
    return __int_as_float(i >= 0 ? i : (i ^ 0x7fffffff));
}
__device__ __forceinline__ void lse_acc(float& m, float& s, float v) {
    if (v > m) { s = s * __expf(m - v) + 1.f; m = v; }
    else       { s += __expf(v - m); }
}
__device__ __forceinline__ void lse_merge(float& m, float& s, float m2, float s2) {
    if (m2 > m) { s = s * __expf(m - m2) + s2; m = m2; }
    else        { s += s2 * __expf(m2 - m); }
}
__device__ __forceinline__ float warp_sum(float v) {
#pragma unroll
    for (int o = 16; o > 0; o >>= 1) v += __shfl_xor_sync(0xffffffffu, v, o);
    return v;
}
__device__ __forceinline__ float warp_max(float v) {
#pragma unroll
    for (int o = 16; o > 0; o >>= 1) v = fmaxf(v, __shfl_xor_sync(0xffffffffu, v, o));
    return v;
}

// ---------------- fp16 utils ----------------
__device__ __forceinline__ void h_split(float x, __half& hi, __half& lo) {
    hi = __float2half_rn(x);
    lo = __float2half_rn(x - __half2float(hi));
}
__device__ __forceinline__ void mma_f16(float4& d, const uint32_t* a, const uint32_t* b) {
    asm volatile(
        "mma.sync.aligned.m16n8k16.row.col.f32.f16.f16.f32 "
        "{%0,%1,%2,%3}, {%4,%5,%6,%7}, {%8,%9}, {%0,%1,%2,%3};"
        : "+f"(d.x), "+f"(d.y), "+f"(d.z), "+f"(d.w)
        : "r"(a[0]), "r"(a[1]), "r"(a[2]), "r"(a[3]), "r"(b[0]), "r"(b[1]));
}
__device__ __forceinline__ void cpasync16(uint32_t dst, const void* src) {
    asm volatile("cp.async.cg.shared.global [%0], [%1], 16;" :: "r"(dst), "l"(src));
}
__device__ __forceinline__ void cp_commit() { asm volatile("cp.async.commit_group;"); }
template <int N> __device__ __forceinline__ void cp_wait() {
    asm volatile("cp.async.wait_group %0;" :: "n"(N));
}

// ---------------- unified prep kernel ----------------
// blocks [0,4096): fp16 presplit 4 matrices (3 embeddings + nsp);
// [4096,4480): wt transpose + fp16 split x6; [4480,8480): ewT transpose; [8480,8512): inits.
struct Prep {
    const float* psrc[4]; __half* phid[4]; __half* plod[4];
    const float* wsrc[6]; __half* whid[6]; __half* wlod[6];
    const float* ew; float* ewt;
    int* rm; float* rsum; float* slg; const float* soutb;
};
__global__ __launch_bounds__(256) void prep_k(Prep P) {
    __shared__ float t[32][33];
    int b = blockIdx.x, tid = threadIdx.x;
    if (b < 4096) {
        int mat = b >> 10;
        int i = (b & 1023) * 256 + tid;
        float4 v = ((const float4*)P.psrc[mat])[i];
        __half hx, lx, hy, ly, hz, lz, hw, lw;
        h_split(v.x, hx, lx); h_split(v.y, hy, ly);
        h_split(v.z, hz, lz); h_split(v.w, hw, lw);
        __half2 h01 = __halves2half2(hx, hy), h23 = __halves2half2(hz, hw);
        __half2 l01 = __halves2half2(lx, ly), l23 = __halves2half2(lz, lw);
        uint2 hv, lv;
        hv.x = *(uint32_t*)&h01; hv.y = *(uint32_t*)&h23;
        lv.x = *(uint32_t*)&l01; lv.y = *(uint32_t*)&l23;
        ((uint2*)P.phid[mat])[i] = hv;
        ((uint2*)P.plod[mat])[i] = lv;
    } else if (b < 4480) {
        int idx = b - 4096;
        int mat = idx >> 6, p = idx & 63;
        int bx = (p & 7) * 32, by = (p >> 3) * 32;
        int x = tid & 31, y = tid >> 5;
        const float* w = P.wsrc[mat];
#pragma unroll
        for (int i = 0; i < 32; i += 8)
            t[y + i][x] = w[(size_t)(by + y + i) * Hh + bx + x];
        __syncthreads();
#pragma unroll
        for (int i = 0; i < 32; i += 8) {
            float v = t[x][y + i];
            __half h, l;
            h_split(v, h, l);
            P.whid[mat][(size_t)(bx + y + i) * Hh + by + x] = h;
            P.wlod[mat][(size_t)(bx + y + i) * Hh + by + x] = l;
        }
    } else if (b < 8480) {
        int p = b - 4480;
        int bx = (p % 500) * 32, by = (p / 500) * 32;
        int x = tid & 31, y = tid >> 5;
#pragma unroll
        for (int i = 0; i < 32; i += 8)
            t[y + i][x] = P.ew[(size_t)(by + y + i) * Vv + bx + x];
        __syncthreads();
#pragma unroll
        for (int i = 0; i < 32; i += 8)
            P.ewt[(size_t)(bx + y + i) * Hh + by + x] = t[x][y + i];
    } else {
        int i = (b - 8480) * 256 + tid;
        if (i < Cc) { P.rm[i] = (int)0x80000000; P.rsum[i] = 0.f; }
        else        { P.slg[i - Cc] = P.soutb[0]; }
    }
}

// ---------------- MLP GEMM: fp16 3-split, m16n8k16, 128x64 tile, pipelined -------
// stage layout (bytes): A mats at mat*6144 + r*48 + c*16; B at 12288 + mat*3072 + r*48 + c*16.
struct PH { const __half *Ah, *Al, *Bh, *Bl; const float *bias, *R, *sw;
            float *C; __half *Oh, *Ol; };
struct PH3 { PH p[3]; };

template <int EPI>
__global__ __launch_bounds__(256) void gemmp_h(PH3 bt, float* __restrict__ slogp, int N) {
    constexpr int NIT = 16, BUFB = 18432;      // bytes per stage
    __shared__ uint32_t smem[2 * BUFB / 4];    // 36 KB
    const PH pp = bt.p[blockIdx.z];
    int tid = threadIdx.x, wid = tid >> 5, lane = tid & 31;
    int gid = lane >> 2, tg = lane & 3;
    int bm = blockIdx.y * 128, bn = blockIdx.x * 64;
    int warp_m = (wid & 3) * 32, warp_n = (wid >> 2) * 32;

    const __half* gsrc[3]; uint32_t doff[3];
#pragma unroll
    for (int i = 0; i < 3; i++) {
        int ch = tid + i * 256;
        if (ch < 512) {
            int mat = ch >> 8, r = (ch >> 1) & 127, c = ch & 1;
            gsrc[i] = (mat ? pp.Al : pp.Ah) + (size_t)(bm + r) * 256 + c * 8;
            doff[i] = mat * 6144 + r * 48 + c * 16;
        } else {
            int idx = ch - 512;
            int mat = idx >> 7, r = (idx >> 1) & 63, c = idx & 1;
            gsrc[i] = (mat ? pp.Bl : pp.Bh) + (size_t)(bn + r) * 256 + c * 8;
            doff[i] = 12288 + mat * 3072 + r * 48 + c * 16;
        }
    }
    uint32_t sbase = (uint32_t)__cvta_generic_to_shared(smem);

    float4 acc[2][4];
#pragma unroll
    for (int i = 0; i < 2; i++)
#pragma unroll
        for (int j = 0; j < 4; j++) acc[i][j] = make_float4(0.f, 0.f, 0.f, 0.f);

    {
#pragma unroll
        for (int i = 0; i < 3; i++) cpasync16(sbase + doff[i], gsrc[i]);
        cp_commit();
    }
    for (int it = 0; it < NIT; it++) {
        if (it + 1 < NIT) {
            uint32_t b = sbase + ((it + 1) & 1) * BUFB;
#pragma unroll
            for (int i = 0; i < 3; i++) cpasync16(b + doff[i], gsrc[i] + (it + 1) * 16);
            cp_commit();
            cp_wait<1>();
        } else {
            cp_wait<0>();
        }
        __syncthreads();
        const uint32_t* buf = smem + (it & 1) * (BUFB / 4);
        // u32 strides: row 12; Ah 0, Al 1536, Bh 3072, Bl 3840
        uint32_t ah[2][4], al[2][4], bh[4][2], bl[4][2];
#pragma unroll
        for (int mt = 0; mt < 2; mt++) {
            int rb = warp_m + mt * 16 + gid;
            ah[mt][0] = buf[rb * 12 + tg];           al[mt][0] = buf[1536 + rb * 12 + tg];
            ah[mt][1] = buf[(rb + 8) * 12 + tg];     al[mt][1] = buf[1536 + (rb + 8) * 12 + tg];
            ah[mt][2] = buf[rb * 12 + tg + 4];       al[mt][2] = buf[1536 + rb * 12 + tg + 4];
            ah[mt][3] = buf[(rb + 8) * 12 + tg + 4]; al[mt][3] = buf[1536 + (rb + 8) * 12 + tg + 4];
        }
#pragma unroll
        for (int nt = 0; nt < 4; nt++) {
            int cb = warp_n + nt * 8 + gid;
            bh[nt][0] = buf[3072 + cb * 12 + tg];     bl[nt][0] = buf[3840 + cb * 12 + tg];
            bh[nt][1] = buf[3072 + cb * 12 + tg + 4]; bl[nt][1] = buf[3840 + cb * 12 + tg + 4];
        }
#pragma unroll
        for (int mt = 0; mt < 2; mt++)
#pragma unroll
            for (int nt = 0; nt < 4; nt++) {
                mma_f16(acc[mt][nt], ah[mt], bh[nt]);
                mma_f16(acc[mt][nt], al[mt], bh[nt]);
                mma_f16(acc[mt][nt], ah[mt], bl[nt]);
            }
        __syncthreads();
    }

#pragma unroll
    for (int mt = 0; mt < 2; mt++) {
        int row0 = bm + warp_m + mt * 16 + gid;
        float pr0 = 0.f, pr8 = 0.f;
#pragma unroll
        for (int nt = 0; nt < 4; nt++) {
            int col = bn + warp_n + nt * 8 + 2 * tg;
            float4 v = acc[mt][nt];
            float b0 = pp.bias[col], b1 = pp.bias[col + 1];
            v.x = fmaxf(v.x + b0, 0.f); v.y = fmaxf(v.y + b1, 0.f);
            v.z = fmaxf(v.z + b0, 0.f); v.w = fmaxf(v.w + b1, 0.f);
            if (EPI == 2) {
                float2 r0 = *(const float2*)&pp.R[(size_t)row0 * N + col];
                float2 r1 = *(const float2*)&pp.R[(size_t)(row0 + 8) * N + col];
                v.x += r0.x; v.y += r0.y; v.z += r1.x; v.w += r1.y;
                if (pp.sw) {
                    float w0 = pp.sw[col], w1 = pp.sw[col + 1];
                    pr0 += v.x * w0 + v.y * w1;
                    pr8 += v.z * w0 + v.w * w1;
                }
            }
            if (pp.C) {
                *(float2*)&pp.C[(size_t)row0 * N + col] = make_float2(v.x, v.y);
                *(float2*)&pp.C[(size_t)(row0 + 8) * N + col] = make_float2(v.z, v.w);
            }
            if (pp.Oh) {
                __half hx, lx, hy, ly, hz, lz, hw, lw;
                h_split(v.x, hx, lx); h_split(v.y, hy, ly);
                h_split(v.z, hz, lz); h_split(v.w, hw, lw);
                *(__half2*)&pp.Oh[(size_t)row0 * N + col] = __halves2half2(hx, hy);
                *(__half2*)&pp.Ol[(size_t)row0 * N + col] = __halves2half2(lx, ly);
                *(__half2*)&pp.Oh[(size_t)(row0 + 8) * N + col] = __halves2half2(hz, hw);
                *(__half2*)&pp.Ol[(size_t)(row0 + 8) * N + col] = __halves2half2(lz, lw);
            }
        }
        if (EPI == 2 && pp.sw) {
            pr0 += __shfl_xor_sync(0xffffffffu, pr0, 1);
            pr0 += __shfl_xor_sync(0xffffffffu, pr0, 2);
            pr8 += __shfl_xor_sync(0xffffffffu, pr8, 1);
            pr8 += __shfl_xor_sync(0xffffffffu, pr8, 2);
            if (tg == 0) {
                atomicAdd(&slogp[row0], pr0);
                atomicAdd(&slogp[row0 + 8], pr8);
            }
        }
    }
}

// ---------------- trans GEMM: fp16 3-split, m16n8k16, 128x128 tile, fused lse --
__global__ __launch_bounds__(256) void gemm2_h(
    const __half* __restrict__ Ahg, const __half* __restrict__ Alg,
    const __half* __restrict__ Bhg, const __half* __restrict__ Blg,
    float* __restrict__ C, float2* __restrict__ part)
{
    constexpr int NIT = 16, BUFB = 24576;
    __shared__ uint32_t smem[2 * BUFB / 4];
    int tid = threadIdx.x, wid = tid >> 5, lane = tid & 31;
    int gid = lane >> 2, tg = lane & 3;
    int bm = blockIdx.y * 128, bn = blockIdx.x * 128;
    int warp_m = (wid & 1) * 64, warp_n = (wid >> 1) * 32;

    const __half* gsrc[4]; uint32_t doff[4];
#pragma unroll
    for (int i = 0; i < 4; i++) {
        int ch = tid + i * 256;
        int mat = ch >> 8;
        int idx = ch & 255, r = idx >> 1, c = idx & 1;
        const __half* g = (mat == 0) ? Ahg : (mat == 1) ? Alg : (mat == 2) ? Bhg : Blg;
        int row = ((mat < 2) ? bm : bn) + r;
        gsrc[i] = g + (size_t)row * 256 + c * 8;
        doff[i] = mat * 6144 + r * 48 + c * 16;
    }
    uint32_t sbase = (uint32_t)__cvta_generic_to_shared(smem);

    float4 acc[4][4];
#pragma unroll
    for (int i = 0; i < 4; i++)
#pragma unroll
        for (int j = 0; j < 4; j++) acc[i][j] = make_float4(0.f, 0.f, 0.f, 0.f);

    {
#pragma unroll
        for (int i = 0; i < 4; i++) cpasync16(sbase + doff[i], gsrc[i]);
        cp_commit();
    }
    for (int it = 0; it < NIT; it++) {
        if (it + 1 < NIT) {
            uint32_t b = sbase + ((it + 1) & 1) * BUFB;
#pragma unroll
            for (int i = 0; i < 4; i++) cpasync16(b + doff[i], gsrc[i] + (it + 1) * 16);
            cp_commit();
            cp_wait<1>();
        } else {
            cp_wait<0>();
        }
        __syncthreads();
        const uint32_t* buf = smem + (it & 1) * (BUFB / 4);
        uint32_t ah[4][4], al[4][4], bh[4][2], bl[4][2];
#pragma unroll
        for (int mt = 0; mt < 4; mt++) {
            int rb = warp_m + mt * 16 + gid;
            ah[mt][0] = buf[rb * 12 + tg];           al[mt][0] = buf[1536 + rb * 12 + tg];
            ah[mt][1] = buf[(rb + 8) * 12 + tg];     al[mt][1] = buf[1536 + (rb + 8) * 12 + tg];
            ah[mt][2] = buf[rb * 12 + tg + 4];       al[mt][2] = buf[1536 + rb * 12 + tg + 4];
            ah[mt][3] = buf[(rb + 8) * 12 + tg + 4]; al[mt][3] = buf[1536 + (rb + 8) * 12 + tg + 4];
        }
#pragma unroll
        for (int nt = 0; nt < 4; nt++) {
            int cb = warp_n + nt * 8 + gid;
            bh[nt][0] = buf[3072 + cb * 12 + tg];     bl[nt][0] = buf[4608 + cb * 12 + tg];
            bh[nt][1] = buf[3072 + cb * 12 + tg + 4]; bl[nt][1] = buf[4608 + cb * 12 + tg + 4];
        }
#pragma unroll
        for (int mt = 0; mt < 4; mt++)
#pragma unroll
            for (int nt = 0; nt < 4; nt++) {
                mma_f16(acc[mt][nt], ah[mt], bh[nt]);
                mma_f16(acc[mt][nt], al[mt], bh[nt]);
                mma_f16(acc[mt][nt], ah[mt], bl[nt]);
            }
        __syncthreads();
    }

    int chunk = blockIdx.x * 4 + (wid >> 1);
#pragma unroll
    for (int mt = 0; mt < 4; mt++) {
        int row0 = bm + warp_m + mt * 16 + gid;
        float m0 = -CUDART_INF_F, s0 = 0.f, m8 = -CUDART_INF_F, s8 = 0.f;
#pragma unroll
        for (int nt = 0; nt < 4; nt++) {
            int col = bn + warp_n + nt * 8 + 2 * tg;
            float4 v = acc[mt][nt];
            *(float2*)&C[(size_t)row0 * Cc + col] = make_float2(v.x, v.y);
            *(float2*)&C[(size_t)(row0 + 8) * Cc + col] = make_float2(v.z, v.w);
            lse_acc(m0, s0, v.x); lse_acc(m0, s0, v.y);
            lse_acc(m8, s8, v.z); lse_acc(m8, s8, v.w);
        }
#pragma unroll
        for (int o = 1; o <= 2; o <<= 1) {
            float m2 = __shfl_xor_sync(0xffffffffu, m0, o);
            float s2 = __shfl_xor_sync(0xffffffffu, s0, o);
            lse_merge(m0, s0, m2, s2);
            m2 = __shfl_xor_sync(0xffffffffu, m8, o);
            s2 = __shfl_xor_sync(0xffffffffu, s8, o);
            lse_merge(m8, s8, m2, s2);
        }
        if (tg == 0) {
            part[(size_t)row0 * 128 + chunk] = make_float2(m0, s0);
            part[(size_t)(row0 + 8) * 128 + chunk] = make_float2(m8, s8);
        }
    }
}

// merge: blocks [0,512) tlse rows; block 512 computes slse from slog
__global__ void merge_k(const float2* __restrict__ part, float* __restrict__ tlse,
                        const float* __restrict__ slog, float* __restrict__ slse) {
    int tid = threadIdx.x;
    if (blockIdx.x < 512) {
        int row = blockIdx.x * 8 + (tid >> 5);
        int lane = tid & 31;
        float m = -CUDART_INF_F, s = 0.f;
#pragma unroll
        for (int i = 0; i < 4; i++) {
            float2 p = part[(size_t)row * 128 + lane + 32 * i];
            lse_merge(m, s, p.x, p.y);
        }
#pragma unroll
        for (int o = 16; o > 0; o >>= 1) {
            float m2 = __shfl_xor_sync(0xffffffffu, m, o);
            float s2 = __shfl_xor_sync(0xffffffffu, s, o);
            lse_merge(m, s, m2, s2);
        }
        if (lane == 0) tlse[row] = m + __logf(s);
    } else {
        float m = -CUDART_INF_F, s = 0.f;
        for (int i = tid; i < Cc; i += 256) lse_acc(m, s, slog[i]);
#pragma unroll
        for (int o = 16; o > 0; o >>= 1) {
            float m2 = __shfl_xor_sync(0xffffffffu, m, o);
            float s2 = __shfl_xor_sync(0xffffffffu, s, o);
            lse_merge(m, s, m2, s2);
        }
        __shared__ float sm[8], ss[8];
        int w = tid >> 5, lane = tid & 31;
        if (lane == 0) { sm[w] = m; ss[w] = s; }
        __syncthreads();
        if (tid == 0) {
            float M = sm[0], S = ss[0];
            for (int i = 1; i < 8; i++) lse_merge(M, S, sm[i], ss[i]);
            slse[0] = M + __logf(S);
        }
    }
}

// sparse emission logits
__global__ __launch_bounds__(256) void emlog_k(
    const float* __restrict__ pre, const float* __restrict__ ewT,
    const float* __restrict__ eb, const int* __restrict__ w2s,
    float* __restrict__ L, int* __restrict__ rowmax)
{
    int v = blockIdx.x;
    __shared__ float4 ecol4[64];
    __shared__ int st[SPW];
    int tid = threadIdx.x;
    if (tid < 64) ecol4[tid] = ((const float4*)(ewT + (size_t)v * Hh))[tid];
    if (tid >= 224) st[tid - 224] = w2s[v * SPW + (tid - 224)];
    __syncthreads();
    int w = tid >> 5, lane = tid & 31;
    float4 e0 = ecol4[lane], e1 = ecol4[lane + 32];
    float bv = eb[v];
#pragma unroll
    for (int q = 0; q < 4; q++) {
        int jj = w + q * 8;
        int c = st[jj];
        const float4* pr = (const float4*)(pre + (size_t)c * Hh);
        float4 p0 = pr[lane], p1 = pr[lane + 32];
        float p = p0.x * e0.x + p0.y * e0.y + p0.z * e0.z + p0.w * e0.w
                + p1.x * e1.x + p1.y * e1.y + p1.z * e1.z + p1.w * e1.w;
        p = warp_sum(p);
        if (lane == 0) {
            float val = p + bv;
            L[v * SPW + jj] = val;
            atomicMax(&rowmax[c], ford(val));
        }
    }
}

__global__ void emsum_k(const int* __restrict__ w2s, const float* __restrict__ L,
                        const int* __restrict__ rm, float* __restrict__ rsum) {
    int gid = blockIdx.x * 256 + threadIdx.x;
    int v = gid >> 5, j = gid & 31;
    int c = w2s[v * SPW + j];
    for (int jp = 0; jp < j; jp++)
        if (w2s[v * SPW + jp] == c) return;
    atomicAdd(&rsum[c], __expf(L[gid] - deord(rm[c])));
}

__global__ void stlse_k(const int* __restrict__ rm, const float* __restrict__ rsum,
                        float* __restrict__ stlse) {
    int i = blockIdx.x * 256 + threadIdx.x;
    if (i < Cc) stlse[i] = deord(rm[i]) + __logf(rsum[i]);
}

// phi with obs/init fused; warp-per-row gather + smem transpose, coalesced write
__global__ __launch_bounds__(1024) void phi_k(
    const int* __restrict__ text, const int* __restrict__ w2s,
    const float* __restrict__ trans, const float* __restrict__ tlse,
    const float* __restrict__ L, const float* __restrict__ stlse,
    const float* __restrict__ slog, const float* __restrict__ slse,
    float* __restrict__ phi)
{
    int b = blockIdx.x;
    int n = b / Tm1, t = b % Tm1;
    __shared__ int c0[SPW], c1[SPW];
    __shared__ float ob1[SPW], iob[SPW], tl0[SPW];
    __shared__ float tile[SPW * 33];
    int tid = threadIdx.x;
    if (tid < SPW) {
        int v0 = text[n * Tt + t], v1 = text[n * Tt + t + 1];
        int cc0 = w2s[v0 * SPW + tid], cc1 = w2s[v1 * SPW + tid];
        c0[tid] = cc0; c1[tid] = cc1;
        tl0[tid] = tlse[cc0];
        ob1[tid] = L[v1 * SPW + tid] - stlse[cc1];
        iob[tid] = (t == 0)
            ? (slog[cc0] - slse[0] + L[v0 * SPW + tid] - stlse[cc0]) : 0.f;
    }
    __syncthreads();
    int jw = tid >> 5, kl = tid & 31;
    float val = __ldg(&trans[(size_t)c0[jw] * Cc + c1[kl]]) - tl0[jw] + ob1[kl] + iob[jw];
    tile[jw * 33 + kl] = val;
    __syncthreads();
    int kw = tid >> 5, jl = tid & 31;
    phi[(size_t)(t * Nn + n) * 1024 + kw * SPW + jl] = tile[jl * 33 + kw];
}

// forward (blocks 0..31) / backward (32..63) scans; 1 barrier per step
__global__ __launch_bounds__(1024) void scan_k(
    const float* __restrict__ phi, float* __restrict__ ap, float* __restrict__ bn,
    float* __restrict__ logZ, float* __restrict__ out)
{
    __shared__ float a_s[2][SPW];
    int tid = threadIdx.x, w = tid >> 5, lane = tid & 31;
    bool bwd = blockIdx.x >= Nn;
    int n = bwd ? (int)blockIdx.x - Nn : (int)blockIdx.x;
    if (tid < SPW) a_s[0][tid] = 0.f;
    __syncthreads();
    int cur = 0;
    if (!bwd) {
        float pv = phi[(size_t)n * 1024 + tid];
        for (int t = 0; t < Tm1; t++) {
            float pvn = (t + 1 < Tm1) ? phi[(size_t)((t + 1) * Nn + n) * 1024 + tid] : 0.f;
            if (tid < SPW) ap[(size_t)(t * Nn + n) * SPW + tid] = a_s[cur][tid];
            float x = pv + a_s[cur][lane];
            float m = warp_max(x);
            float s = warp_sum(__expf(x - m));
            if (lane == 0) a_s[cur ^ 1][w] = m + __logf(s);
            __syncthreads();
            cur ^= 1;
            pv = pvn;
        }
        if (w == 0) {
            float x = a_s[cur][lane];
            float m = warp_max(x);
            float s = warp_sum(__expf(x - m));
            float lz = m + __logf(s);
            if (lane == 0) logZ[n] = lz;
            out[2 + n * SPW + lane] = x - lz;
        }
        if (n == 0 && tid == 1023) out[0] = 0.f;
    } else {
        float pv = phi[(size_t)((Tm1 - 1) * Nn + n) * 1024 + lane * SPW + w];
        for (int t = Tm1 - 1; t >= 0; t--) {
            float pvn = (t > 0) ? phi[(size_t)((t - 1) * Nn + n) * 1024 + lane * SPW + w] : 0.f;
            if (tid < SPW) bn[(size_t)(t * Nn + n) * SPW + tid] = a_s[cur][tid];
            float x = pv + a_s[cur][lane];
            float m = warp_max(x);
            float s = warp_sum(__expf(x - m));
            if (lane == 0) a_s[cur ^ 1][w] = m + __logf(s);
            __syncthreads();
            cur ^= 1;
            pv = pvn;
        }
    }
}

// elbo + evidence fused
__global__ __launch_bounds__(1024) void elbo_k(
    const float* __restrict__ phi, const float* __restrict__ ap,
    const float* __restrict__ bn, const float* __restrict__ logZ,
    float* __restrict__ out)
{
    int e = blockIdx.x;
    int n = e % Nn;
    __shared__ float sap[SPW], sbn[SPW], ws[32];
    int tid = threadIdx.x;
    if (tid < SPW) { sap[tid] = ap[(size_t)e * SPW + tid]; sbn[tid] = bn[(size_t)e * SPW + tid]; }
    __syncthreads();
    int k = tid >> 5, j = tid & 31;
    float p = phi[(size_t)e * 1024 + tid];
    float term = __expf(sap[j] + p + sbn[k] - logZ[n]) * p;
    term = warp_sum(term);
    if (j == 0) ws[k] = term;
    __syncthreads();
    if (tid < 32) {
        float v = warp_sum(ws[tid]);
        if (tid == 0) atomicAdd(&out[0], v);
    }
    if (e == 0 && tid >= 64 && tid < 96) {
        int lane2 = tid - 64;
        float lz = logZ[lane2];
        lz = warp_sum(lz);
        if (lane2 == 0) out[1] = lz;
    }
}

// ---------------- launcher ----------------
extern "C" void kernel_launch(void* const* d_in, const int* in_sizes, int n_in,
                              void* d_out, int out_size) {
    const float* start_emb = (const float*)d_in[0];
    const float* sw1  = (const float*)d_in[1];
    const float* sb1  = (const float*)d_in[2];
    const float* sw2  = (const float*)d_in[3];
    const float* sb2  = (const float*)d_in[4];
    const float* s_out_w = (const float*)d_in[5];
    const float* s_out_b = (const float*)d_in[6];
    const float* state_emb = (const float*)d_in[7];
    const float* tw1  = (const float*)d_in[8];
    const float* tb1  = (const float*)d_in[9];
    const float* tw2  = (const float*)d_in[10];
    const float* tb2  = (const float*)d_in[11];
    const float* nsp  = (const float*)d_in[12];
    const float* pre_emb = (const float*)d_in[13];
    const float* ew1  = (const float*)d_in[14];
    const float* eb1  = (const float*)d_in[15];
    const float* ew2  = (const float*)d_in[16];
    const float* eb2  = (const float*)d_in[17];
    const float* e_out_w = (const float*)d_in[18];
    const float* e_out_b = (const float*)d_in[19];
    const int* text = (const int*)d_in[20];
    const int* w2s  = (const int*)d_in[21];
    float* out = (float*)d_out;

    float* S = nullptr; int* RM = nullptr; uint32_t* U = nullptr;
    cudaGetSymbolAddress((void**)&S, g_scr);
    cudaGetSymbolAddress((void**)&RM, g_rowmax);
    cudaGetSymbolAddress((void**)&U, g_u);

    static bool inited = false;
    static cudaStream_t s1;
    static cudaEvent_t evB2, evEm;
    if (!inited) {
        cudaStreamCreateWithFlags(&s1, cudaStreamNonBlocking);
        cudaEventCreateWithFlags(&evB2, cudaEventDisableTiming);
        cudaEventCreateWithFlags(&evEm, cudaEventDisableTiming);
        inited = true;
    }

    // ---- prep ----
    Prep P;
    const float* em_[4] = { start_emb, state_emb, pre_emb, nsp };
    for (int j = 0; j < 3; j++) {
        P.psrc[j] = em_[j];
        P.phid[j] = (__half*)(U + HEMB + (size_t)j * 2 * HS);
        P.plod[j] = (__half*)(U + HEMB + (size_t)j * 2 * HS + HS);
    }
    P.psrc[3] = nsp;
    P.phid[3] = (__half*)(U + NSPh);
    P.plod[3] = (__half*)(U + NSPl);
    const float* ws_[6] = { sw1, tw1, ew1, sw2, tw2, ew2 };
    for (int j = 0; j < 6; j++) {
        P.wsrc[j] = ws_[j];
        P.whid[j] = (__half*)(U + HWB + (size_t)j * 2 * HWS);
        P.wlod[j] = (__half*)(U + HWB + (size_t)j * 2 * HWS + HWS);
    }
    P.ew = e_out_w; P.ewt = S + OFF_EWT;
    P.rm = RM; P.rsum = S + OFF_RSUM; P.slg = S + OFF_SLOG; P.soutb = s_out_b;
    prep_k<<<8512, 256>>>(P);

    // ---- MLPs (fp16 3-split) ----
    const float* b1_[3] = { sb1, tb1, eb1 };
    PH3 m1;
    for (int j = 0; j < 3; j++) {
        PH& q = m1.p[j];
        q.Ah = (const __half*)(U + HEMB + (size_t)j * 2 * HS);
        q.Al = (const __half*)(U + HEMB + (size_t)j * 2 * HS + HS);
        q.Bh = (const __half*)(U + HWB + (size_t)j * 2 * HWS);
        q.Bl = (const __half*)(U + HWB + (size_t)j * 2 * HWS + HWS);
        q.bias = b1_[j]; q.R = nullptr; q.sw = nullptr; q.C = nullptr;
        q.Oh = (__half*)(U + HOUT + (size_t)j * 2 * HS);
        q.Ol = (__half*)(U + HOUT + (size_t)j * 2 * HS + HS);
    }
    gemmp_h<1><<<dim3(Hh / 64, Cc / 128, 3), 256>>>(m1, nullptr, Hh);

    PH3 m2;
    {
        PH& q = m2.p[0];
        q.Ah = (const __half*)(U + HOUT + 0 * HS);
        q.Al = (const __half*)(U + HOUT + 1 * HS);
        q.Bh = (const __half*)(U + HWB + 3 * 2 * HWS);
        q.Bl = (const __half*)(U + HWB + 3 * 2 * HWS + HWS);
        q.bias = sb2; q.R = start_emb; q.sw = s_out_w;
        q.C = S + OFF_RS; q.Oh = nullptr; q.Ol = nullptr;
    }
    {
        PH& q = m2.p[1];
        q.Ah = (const __half*)(U + HOUT + 2 * HS);
        q.Al = (const __half*)(U + HOUT + 3 * HS);
        q.Bh = (const __half*)(U + HWB + 4 * 2 * HWS);
        q.Bl = (const __half*)(U + HWB + 4 * 2 * HWS + HWS);
        q.bias = tb2; q.R = state_emb; q.sw = nullptr;
        q.C = nullptr;
        q.Oh = (__half*)(U + RSTh); q.Ol = (__half*)(U + RSTl);
    }
    {
        PH& q = m2.p[2];
        q.Ah = (const __half*)(U + HOUT + 4 * HS);
        q.Al = (const __half*)(U + HOUT + 5 * HS);
        q.Bh = (const __half*)(U + HWB + 5 * 2 * HWS);
        q.Bl = (const __half*)(U + HWB + 5 * 2 * HWS + HWS);
        q.bias = eb2; q.R = pre_emb; q.sw = nullptr;
        q.C = S + OFF_RP; q.Oh = nullptr; q.Ol = nullptr;
    }
    gemmp_h<2><<<dim3(Hh / 64, Cc / 128, 3), 256>>>(m2, S + OFF_SLOG, Hh);
    cudaEventRecord(evB2, 0);

    // ---- s1: emission chain (concurrent with trans GEMM) ----
    cudaStreamWaitEvent(s1, evB2, 0);
    emlog_k<<<Vv, 256, 0, s1>>>(S + OFF_RP, S + OFF_EWT, e_out_b, w2s, S + OFF_L, RM);
    emsum_k<<<Vv * SPW / 256, 256, 0, s1>>>(w2s, S + OFF_L, RM, S + OFF_RSUM);
    stlse_k<<<16, 256, 0, s1>>>(RM, S + OFF_RSUM, S + OFF_STLSE);
    cudaEventRecord(evEm, s1);

    // ---- main: fp16 trans GEMM + merged lse reductions ----
    gemm2_h<<<dim3(Cc / 128, Cc / 128), 256>>>(
        (const __half*)(U + RSTh), (const __half*)(U + RSTl),
        (const __half*)(U + NSPh), (const __half*)(U + NSPl),
        S + OFF_TRANS, (float2*)(S + OFF_PART));
    merge_k<<<513, 256>>>((float2*)(S + OFF_PART), S + OFF_TLSE, S + OFF_SLOG, S + OFF_SLSE);

    // ---- join + tail ----
    cudaStreamWaitEvent(0, evEm, 0);
    phi_k<<<Nn * Tm1, 1024>>>(text, w2s, S + OFF_TRANS, S + OFF_TLSE,
                              S + OFF_L, S + OFF_STLSE, S + OFF_SLOG, S + OFF_SLSE,
                              S + OFF_PHI);
    scan_k<<<2 * Nn, 1024>>>(S + OFF_PHI, S + OFF_AP, S + OFF_BN, S + OFF_LOGZ, out);
    elbo_k<<<Tm1 * Nn, 1024>>>(S + OFF_PHI, S + OFF_AP, S + OFF_BN, S + OFF_LOGZ, out);
}

// round 10
// speedup vs baseline: 1.3826x; 1.0164x over previous
#include <cuda_runtime.h>
#include <cuda_fp16.h>
#include <math_constants.h>
#include <cstdint>
#include <cstddef>

static constexpr int Vv = 16000, Cc = 4096, Hh = 256, SPW = 32, Nn = 32, Tt = 128, Tm1 = 127;

// ---------------- scratch layout ----------------
constexpr size_t SZ_MAT   = (size_t)Cc * Hh;                  // 1,048,576
constexpr size_t OFF_RS   = 0;
constexpr size_t OFF_RP   = OFF_RS   + SZ_MAT;
constexpr size_t OFF_TRANS= OFF_RP   + SZ_MAT;                // 4096x4096
constexpr size_t OFF_TLSE = OFF_TRANS+ (size_t)Cc * Cc;
constexpr size_t OFF_SLOG = OFF_TLSE + Cc;
constexpr size_t OFF_SLSE = OFF_SLOG + Cc;
constexpr size_t OFF_EWT  = OFF_SLSE + 32;                    // V x H
constexpr size_t OFF_L    = OFF_EWT  + (size_t)Vv * Hh;       // V x SPW
constexpr size_t OFF_RSUM = OFF_L    + (size_t)Vv * SPW;
constexpr size_t OFF_STLSE= OFF_RSUM + Cc;
constexpr size_t OFF_PHI  = OFF_STLSE+ Cc;                    // Tm1*N*32*32
constexpr size_t OFF_AP   = OFF_PHI  + (size_t)Tm1 * Nn * SPW * SPW;
constexpr size_t OFF_BN   = OFF_AP   + (size_t)Tm1 * Nn * SPW;
constexpr size_t OFF_LOGZ = OFF_BN   + (size_t)Tm1 * Nn * SPW;
constexpr size_t OFF_PART = OFF_LOGZ + 64;                    // 4096 x 128 x (m,s)
constexpr size_t SCRATCH_TOTAL = OFF_PART + (size_t)Cc * 128 * 2;

__device__ float g_scr[SCRATCH_TOTAL];
__device__ int   g_rowmax[Cc];

// fp16 split buffers (u32 units; aliased as __half)
constexpr size_t WSZ = (size_t)Hh * Hh;                       // 65536
constexpr size_t HS  = SZ_MAT / 2;                            // u32 per half-matrix
constexpr size_t HWS = WSZ / 2;                               // u32 per half weight
constexpr size_t RSTh = 0, RSTl = HS;
constexpr size_t NSPh = 2 * HS, NSPl = 3 * HS;
constexpr size_t HEMB = 4 * HS;                               // 3 x (hi,lo) embeddings
constexpr size_t HOUT = 10 * HS;                              // 3 x (hi,lo) H outputs
constexpr size_t HWB  = 16 * HS;                              // 6 x (hi,lo) weights
__device__ uint32_t g_u[16 * HS + 12 * HWS];

// ---------------- helpers ----------------
__device__ __forceinline__ int ford(float f) {
    int i = __float_as_int(f);
    return i >= 0 ? i : (i ^ 0x7fffffff);
}
__device__ __forceinline__ float deord(int i) {
    return __int_as_float(i >= 0 ? i : (i ^ 0x7fffffff));
}
__device__ __forceinline__ void lse_acc(float& m, float& s, float v) {
    if (v > m) { s = s * __expf(m - v) + 1.f; m = v; }
    else       { s += __expf(v - m); }
}
__device__ __forceinline__ void lse_merge(float& m, float& s, float m2, float s2) {
    if (m2 > m) { s = s * __expf(m - m2) + s2; m = m2; }
    else        { s += s2 * __expf(m2 - m); }
}
__device__ __forceinline__ float warp_sum(float v) {
#pragma unroll
    for (int o = 16; o > 0; o >>= 1) v += __shfl_xor_sync(0xffffffffu, v, o);
    return v;
}
__device__ __forceinline__ float warp_max(float v) {
#pragma unroll
    for (int o = 16; o > 0; o >>= 1) v = fmaxf(v, __shfl_xor_sync(0xffffffffu, v, o));
    return v;
}

// ---------------- fp16 utils ----------------
__device__ __forceinline__ void h_split(float x, __half& hi, __half& lo) {
    hi = __float2half_rn(x);
    lo = __float2half_rn(x - __half2float(hi));
}
__device__ __forceinline__ void mma_f16(float4& d, const uint32_t* a, const uint32_t* b) {
    asm volatile(
        "mma.sync.aligned.m16n8k16.row.col.f32.f16.f16.f32 "
        "{%0,%1,%2,%3}, {%4,%5,%6,%7}, {%8,%9}, {%0,%1,%2,%3};"
        : "+f"(d.x), "+f"(d.y), "+f"(d.z), "+f"(d.w)
        : "r"(a[0]), "r"(a[1]), "r"(a[2]), "r"(a[3]), "r"(b[0]), "r"(b[1]));
}
__device__ __forceinline__ void ldsm4(uint32_t& r0, uint32_t& r1, uint32_t& r2, uint32_t& r3,
                                      uint32_t addr) {
    asm volatile("ldmatrix.sync.aligned.m8n8.x4.shared.b16 {%0,%1,%2,%3}, [%4];"
                 : "=r"(r0), "=r"(r1), "=r"(r2), "=r"(r3) : "r"(addr));
}
__device__ __forceinline__ void cpasync16(uint32_t dst, const void* src) {
    asm volatile("cp.async.cg.shared.global [%0], [%1], 16;" :: "r"(dst), "l"(src));
}
__device__ __forceinline__ void cp_commit() { asm volatile("cp.async.commit_group;"); }
template <int N> __device__ __forceinline__ void cp_wait() {
    asm volatile("cp.async.wait_group %0;" :: "n"(N));
}

// ---------------- prep kernels ----------------
// prep_k: [0,4096) fp16 presplit 4 matrices; [4096,4480) wt transpose + split x6.
struct Prep {
    const float* psrc[4]; __half* phid[4]; __half* plod[4];
    const float* wsrc[6]; __half* whid[6]; __half* wlod[6];
};
__global__ __launch_bounds__(256) void prep_k(Prep P) {
    __shared__ float t[32][33];
    int b = blockIdx.x, tid = threadIdx.x;
    if (b < 4096) {
        int mat = b >> 10;
        int i = (b & 1023) * 256 + tid;
        float4 v = ((const float4*)P.psrc[mat])[i];
        __half hx, lx, hy, ly, hz, lz, hw, lw;
        h_split(v.x, hx, lx); h_split(v.y, hy, ly);
        h_split(v.z, hz, lz); h_split(v.w, hw, lw);
        __half2 h01 = __halves2half2(hx, hy), h23 = __halves2half2(hz, hw);
        __half2 l01 = __halves2half2(lx, ly), l23 = __halves2half2(lz, lw);
        uint2 hv, lv;
        hv.x = *(uint32_t*)&h01; hv.y = *(uint32_t*)&h23;
        lv.x = *(uint32_t*)&l01; lv.y = *(uint32_t*)&l23;
        ((uint2*)P.phid[mat])[i] = hv;
        ((uint2*)P.plod[mat])[i] = lv;
    } else {
        int idx = b - 4096;
        int mat = idx >> 6, p = idx & 63;
        int bx = (p & 7) * 32, by = (p >> 3) * 32;
        int x = tid & 31, y = tid >> 5;
        const float* w = P.wsrc[mat];
#pragma unroll
        for (int i = 0; i < 32; i += 8)
            t[y + i][x] = w[(size_t)(by + y + i) * Hh + bx + x];
        __syncthreads();
#pragma unroll
        for (int i = 0; i < 32; i += 8) {
            float v = t[x][y + i];
            __half h, l;
            h_split(v, h, l);
            P.whid[mat][(size_t)(bx + y + i) * Hh + by + x] = h;
            P.wlod[mat][(size_t)(bx + y + i) * Hh + by + x] = l;
        }
    }
}

// prep2_k (on s1, overlapped with MLPs): [0,4000) ewT transpose; [4000,4032) inits.
__global__ __launch_bounds__(256) void prep2_k(
    const float* __restrict__ ew, float* __restrict__ ewt,
    int* __restrict__ rm, float* __restrict__ rsum,
    float* __restrict__ slg, const float* __restrict__ soutb)
{
    __shared__ float t[32][33];
    int b = blockIdx.x, tid = threadIdx.x;
    if (b < 4000) {
        int bx = (b % 500) * 32, by = (b / 500) * 32;
        int x = tid & 31, y = tid >> 5;
#pragma unroll
        for (int i = 0; i < 32; i += 8)
            t[y + i][x] = ew[(size_t)(by + y + i) * Vv + bx + x];
        __syncthreads();
#pragma unroll
        for (int i = 0; i < 32; i += 8)
            ewt[(size_t)(bx + y + i) * Hh + by + x] = t[x][y + i];
    } else {
        int i = (b - 4000) * 256 + tid;
        if (i < Cc) { rm[i] = (int)0x80000000; rsum[i] = 0.f; }
        else        { slg[i - Cc] = soutb[0]; }
    }
}

// ---------------- MLP GEMM: fp16 3-split, ldmatrix, 128x64 tile -------
// stage layout (bytes): Ah 0, Al 6144, Bh 12288, Bl 15360; rows padded 48B.
struct PH { const __half *Ah, *Al, *Bh, *Bl; const float *bias, *R, *sw;
            float *C; __half *Oh, *Ol; };
struct PH3 { PH p[3]; };

template <int EPI>
__global__ __launch_bounds__(256) void gemmp_h(PH3 bt, float* __restrict__ slogp, int N) {
    constexpr int NIT = 16, BUFB = 18432;
    __shared__ uint32_t smem[2 * BUFB / 4];
    const PH pp = bt.p[blockIdx.z];
    int tid = threadIdx.x, wid = tid >> 5, lane = tid & 31;
    int gid = lane >> 2, tg = lane & 3;
    int bm = blockIdx.y * 128, bn = blockIdx.x * 64;
    int warp_m = (wid & 3) * 32, warp_n = (wid >> 2) * 32;

    const __half* gsrc[3]; uint32_t doff[3];
#pragma unroll
    for (int i = 0; i < 3; i++) {
        int ch = tid + i * 256;
        if (ch < 512) {
            int mat = ch >> 8, r = (ch >> 1) & 127, c = ch & 1;
            gsrc[i] = (mat ? pp.Al : pp.Ah) + (size_t)(bm + r) * 256 + c * 8;
            doff[i] = mat * 6144 + r * 48 + c * 16;
        } else {
            int idx = ch - 512;
            int mat = idx >> 7, r = (idx >> 1) & 63, c = idx & 1;
            gsrc[i] = (mat ? pp.Bl : pp.Bh) + (size_t)(bn + r) * 256 + c * 8;
            doff[i] = 12288 + mat * 3072 + r * 48 + c * 16;
        }
    }
    uint32_t sbase = (uint32_t)__cvta_generic_to_shared(smem);
    int lr = lane & 7, lg = lane >> 3;
    uint32_t a_off = (uint32_t)(((lg & 1) * 8 + lr) * 48 + (lg >> 1) * 16);
    uint32_t b_off = (uint32_t)(((lg >> 1) * 8 + lr) * 48 + (lg & 1) * 16);

    float4 acc[2][4];
#pragma unroll
    for (int i = 0; i < 2; i++)
#pragma unroll
        for (int j = 0; j < 4; j++) acc[i][j] = make_float4(0.f, 0.f, 0.f, 0.f);

    {
#pragma unroll
        for (int i = 0; i < 3; i++) cpasync16(sbase + doff[i], gsrc[i]);
        cp_commit();
    }
    for (int it = 0; it < NIT; it++) {
        if (it + 1 < NIT) {
            uint32_t b = sbase + ((it + 1) & 1) * BUFB;
#pragma unroll
            for (int i = 0; i < 3; i++) cpasync16(b + doff[i], gsrc[i] + (it + 1) * 16);
            cp_commit();
            cp_wait<1>();
        } else {
            cp_wait<0>();
        }
        __syncthreads();
        uint32_t bufb = sbase + (it & 1) * BUFB;
        uint32_t ah[2][4], al[2][4], bh[4][2], bl[4][2];
#pragma unroll
        for (int mt = 0; mt < 2; mt++) {
            uint32_t ab = bufb + (uint32_t)((warp_m + mt * 16) * 48) + a_off;
            ldsm4(ah[mt][0], ah[mt][1], ah[mt][2], ah[mt][3], ab);
            ldsm4(al[mt][0], al[mt][1], al[mt][2], al[mt][3], ab + 6144);
        }
#pragma unroll
        for (int np = 0; np < 2; np++) {
            uint32_t bb = bufb + 12288u + (uint32_t)((warp_n + np * 16) * 48) + b_off;
            ldsm4(bh[2 * np][0], bh[2 * np][1], bh[2 * np + 1][0], bh[2 * np + 1][1], bb);
            ldsm4(bl[2 * np][0], bl[2 * np][1], bl[2 * np + 1][0], bl[2 * np + 1][1], bb + 3072);
        }
#pragma unroll
        for (int mt = 0; mt < 2; mt++)
#pragma unroll
            for (int nt = 0; nt < 4; nt++) {
                mma_f16(acc[mt][nt], ah[mt], bh[nt]);
                mma_f16(acc[mt][nt], al[mt], bh[nt]);
                mma_f16(acc[mt][nt], ah[mt], bl[nt]);
            }
        __syncthreads();
    }

#pragma unroll
    for (int mt = 0; mt < 2; mt++) {
        int row0 = bm + warp_m + mt * 16 + gid;
        float pr0 = 0.f, pr8 = 0.f;
#pragma unroll
        for (int nt = 0; nt < 4; nt++) {
            int col = bn + warp_n + nt * 8 + 2 * tg;
            float4 v = acc[mt][nt];
            float b0 = pp.bias[col], b1 = pp.bias[col + 1];
            v.x = fmaxf(v.x + b0, 0.f); v.y = fmaxf(v.y + b1, 0.f);
            v.z = fmaxf(v.z + b0, 0.f); v.w = fmaxf(v.w + b1, 0.f);
            if (EPI == 2) {
                float2 r0 = *(const float2*)&pp.R[(size_t)row0 * N + col];
                float2 r1 = *(const float2*)&pp.R[(size_t)(row0 + 8) * N + col];
                v.x += r0.x; v.y += r0.y; v.z += r1.x; v.w += r1.y;
                if (pp.sw) {
                    float w0 = pp.sw[col], w1 = pp.sw[col + 1];
                    pr0 += v.x * w0 + v.y * w1;
                    pr8 += v.z * w0 + v.w * w1;
                }
            }
            if (pp.C) {
                *(float2*)&pp.C[(size_t)row0 * N + col] = make_float2(v.x, v.y);
                *(float2*)&pp.C[(size_t)(row0 + 8) * N + col] = make_float2(v.z, v.w);
            }
            if (pp.Oh) {
                __half hx, lx, hy, ly, hz, lz, hw, lw;
                h_split(v.x, hx, lx); h_split(v.y, hy, ly);
                h_split(v.z, hz, lz); h_split(v.w, hw, lw);
                *(__half2*)&pp.Oh[(size_t)row0 * N + col] = __halves2half2(hx, hy);
                *(__half2*)&pp.Ol[(size_t)row0 * N + col] = __halves2half2(lx, ly);
                *(__half2*)&pp.Oh[(size_t)(row0 + 8) * N + col] = __halves2half2(hz, hw);
                *(__half2*)&pp.Ol[(size_t)(row0 + 8) * N + col] = __halves2half2(lz, lw);
            }
        }
        if (EPI == 2 && pp.sw) {
            pr0 += __shfl_xor_sync(0xffffffffu, pr0, 1);
            pr0 += __shfl_xor_sync(0xffffffffu, pr0, 2);
            pr8 += __shfl_xor_sync(0xffffffffu, pr8, 1);
            pr8 += __shfl_xor_sync(0xffffffffu, pr8, 2);
            if (tg == 0) {
                atomicAdd(&slogp[row0], pr0);
                atomicAdd(&slogp[row0 + 8], pr8);
            }
        }
    }
}

// ---------------- trans GEMM: fp16 3-split, ldmatrix, 128x128 tile, fused lse --
// stage layout (bytes): Ah 0, Al 6144, Bh 12288, Bl 18432.
__global__ __launch_bounds__(256) void gemm2_h(
    const __half* __restrict__ Ahg, const __half* __restrict__ Alg,
    const __half* __restrict__ Bhg, const __half* __restrict__ Blg,
    float* __restrict__ C, float2* __restrict__ part)
{
    constexpr int NIT = 16, BUFB = 24576;
    __shared__ uint32_t smem[2 * BUFB / 4];
    int tid = threadIdx.x, wid = tid >> 5, lane = tid & 31;
    int gid = lane >> 2, tg = lane & 3;
    int bm = blockIdx.y * 128, bn = blockIdx.x * 128;
    int warp_m = (wid & 1) * 64, warp_n = (wid >> 1) * 32;

    const __half* gsrc[4]; uint32_t doff[4];
#pragma unroll
    for (int i = 0; i < 4; i++) {
        int ch = tid + i * 256;
        int mat = ch >> 8;
        int idx = ch & 255, r = idx >> 1, c = idx & 1;
        const __half* g = (mat == 0) ? Ahg : (mat == 1) ? Alg : (mat == 2) ? Bhg : Blg;
        int row = ((mat < 2) ? bm : bn) + r;
        gsrc[i] = g + (size_t)row * 256 + c * 8;
        doff[i] = mat * 6144 + r * 48 + c * 16;
    }
    uint32_t sbase = (uint32_t)__cvta_generic_to_shared(smem);
    int lr = lane & 7, lg = lane >> 3;
    uint32_t a_off = (uint32_t)(((lg & 1) * 8 + lr) * 48 + (lg >> 1) * 16);
    uint32_t b_off = (uint32_t)(((lg >> 1) * 8 + lr) * 48 + (lg & 1) * 16);

    float4 acc[4][4];
#pragma unroll
    for (int i = 0; i < 4; i++)
#pragma unroll
        for (int j = 0; j < 4; j++) acc[i][j] = make_float4(0.f, 0.f, 0.f, 0.f);

    {
#pragma unroll
        for (int i = 0; i < 4; i++) cpasync16(sbase + doff[i], gsrc[i]);
        cp_commit();
    }
    for (int it = 0; it < NIT; it++) {
        if (it + 1 < NIT) {
            uint32_t b = sbase + ((it + 1) & 1) * BUFB;
#pragma unroll
            for (int i = 0; i < 4; i++) cpasync16(b + doff[i], gsrc[i] + (it + 1) * 16);
            cp_commit();
            cp_wait<1>();
        } else {
            cp_wait<0>();
        }
        __syncthreads();
        uint32_t bufb = sbase + (it & 1) * BUFB;
        uint32_t ah[4][4], al[4][4], bh[4][2], bl[4][2];
#pragma unroll
        for (int mt = 0; mt < 4; mt++) {
            uint32_t ab = bufb + (uint32_t)((warp_m + mt * 16) * 48) + a_off;
            ldsm4(ah[mt][0], ah[mt][1], ah[mt][2], ah[mt][3], ab);
            ldsm4(al[mt][0], al[mt][1], al[mt][2], al[mt][3], ab + 6144);
        }
#pragma unroll
        for (int np = 0; np < 2; np++) {
            uint32_t bb = bufb + 12288u + (uint32_t)((warp_n + np * 16) * 48) + b_off;
            ldsm4(bh[2 * np][0], bh[2 * np][1], bh[2 * np + 1][0], bh[2 * np + 1][1], bb);
            ldsm4(bl[2 * np][0], bl[2 * np][1], bl[2 * np + 1][0], bl[2 * np + 1][1], bb + 6144);
        }
#pragma unroll
        for (int mt = 0; mt < 4; mt++)
#pragma unroll
            for (int nt = 0; nt < 4; nt++) {
                mma_f16(acc[mt][nt], ah[mt], bh[nt]);
                mma_f16(acc[mt][nt], al[mt], bh[nt]);
                mma_f16(acc[mt][nt], ah[mt], bl[nt]);
            }
        __syncthreads();
    }

    int chunk = blockIdx.x * 4 + (wid >> 1);
#pragma unroll
    for (int mt = 0; mt < 4; mt++) {
        int row0 = bm + warp_m + mt * 16 + gid;
        float m0 = -CUDART_INF_F, s0 = 0.f, m8 = -CUDART_INF_F, s8 = 0.f;
#pragma unroll
        for (int nt = 0; nt < 4; nt++) {
            int col = bn + warp_n + nt * 8 + 2 * tg;
            float4 v = acc[mt][nt];
            *(float2*)&C[(size_t)row0 * Cc + col] = make_float2(v.x, v.y);
            *(float2*)&C[(size_t)(row0 + 8) * Cc + col] = make_float2(v.z, v.w);
            lse_acc(m0, s0, v.x); lse_acc(m0, s0, v.y);
            lse_acc(m8, s8, v.z); lse_acc(m8, s8, v.w);
        }
#pragma unroll
        for (int o = 1; o <= 2; o <<= 1) {
            float m2 = __shfl_xor_sync(0xffffffffu, m0, o);
            float s2 = __shfl_xor_sync(0xffffffffu, s0, o);
            lse_merge(m0, s0, m2, s2);
            m2 = __shfl_xor_sync(0xffffffffu, m8, o);
            s2 = __shfl_xor_sync(0xffffffffu, s8, o);
            lse_merge(m8, s8, m2, s2);
        }
        if (tg == 0) {
            part[(size_t)row0 * 128 + chunk] = make_float2(m0, s0);
            part[(size_t)(row0 + 8) * 128 + chunk] = make_float2(m8, s8);
        }
    }
}

// merge: blocks [0,512) tlse rows; block 512 computes slse from slog
__global__ void merge_k(const float2* __restrict__ part, float* __restrict__ tlse,
                        const float* __restrict__ slog, float* __restrict__ slse) {
    int tid = threadIdx.x;
    if (blockIdx.x < 512) {
        int row = blockIdx.x * 8 + (tid >> 5);
        int lane = tid & 31;
        float m = -CUDART_INF_F, s = 0.f;
#pragma unroll
        for (int i = 0; i < 4; i++) {
            float2 p = part[(size_t)row * 128 + lane + 32 * i];
            lse_merge(m, s, p.x, p.y);
        }
#pragma unroll
        for (int o = 16; o > 0; o >>= 1) {
            float m2 = __shfl_xor_sync(0xffffffffu, m, o);
            float s2 = __shfl_xor_sync(0xffffffffu, s, o);
            lse_merge(m, s, m2, s2);
        }
        if (lane == 0) tlse[row] = m + __logf(s);
    } else {
        float m = -CUDART_INF_F, s = 0.f;
        for (int i = tid; i < Cc; i += 256) lse_acc(m, s, slog[i]);
#pragma unroll
        for (int o = 16; o > 0; o >>= 1) {
            float m2 = __shfl_xor_sync(0xffffffffu, m, o);
            float s2 = __shfl_xor_sync(0xffffffffu, s, o);
            lse_merge(m, s, m2, s2);
        }
        __shared__ float sm[8], ss[8];
        int w = tid >> 5, lane = tid & 31;
        if (lane == 0) { sm[w] = m; ss[w] = s; }
        __syncthreads();
        if (tid == 0) {
            float M = sm[0], S = ss[0];
            for (int i = 1; i < 8; i++) lse_merge(M, S, sm[i], ss[i]);
            slse[0] = M + __logf(S);
        }
    }
}

// sparse emission logits
__global__ __launch_bounds__(256) void emlog_k(
    const float* __restrict__ pre, const float* __restrict__ ewT,
    const float* __restrict__ eb, const int* __restrict__ w2s,
    float* __restrict__ L, int* __restrict__ rowmax)
{
    int v = blockIdx.x;
    __shared__ float4 ecol4[64];
    __shared__ int st[SPW];
    int tid = threadIdx.x;
    if (tid < 64) ecol4[tid] = ((const float4*)(ewT + (size_t)v * Hh))[tid];
    if (tid >= 224) st[tid - 224] = w2s[v * SPW + (tid - 224)];
    __syncthreads();
    int w = tid >> 5, lane = tid & 31;
    float4 e0 = ecol4[lane], e1 = ecol4[lane + 32];
    float bv = eb[v];
#pragma unroll
    for (int q = 0; q < 4; q++) {
        int jj = w + q * 8;
        int c = st[jj];
        const float4* pr = (const float4*)(pre + (size_t)c * Hh);
        float4 p0 = pr[lane], p1 = pr[lane + 32];
        float p = p0.x * e0.x + p0.y * e0.y + p0.z * e0.z + p0.w * e0.w
                + p1.x * e1.x + p1.y * e1.y + p1.z * e1.z + p1.w * e1.w;
        p = warp_sum(p);
        if (lane == 0) {
            float val = p + bv;
            L[v * SPW + jj] = val;
            atomicMax(&rowmax[c], ford(val));
        }
    }
}

__global__ void emsum_k(const int* __restrict__ w2s, const float* __restrict__ L,
                        const int* __restrict__ rm, float* __restrict__ rsum) {
    int gid = blockIdx.x * 256 + threadIdx.x;
    int v = gid >> 5, j = gid & 31;
    int c = w2s[v * SPW + j];
    for (int jp = 0; jp < j; jp++)
        if (w2s[v * SPW + jp] == c) return;
    atomicAdd(&rsum[c], __expf(L[gid] - deord(rm[c])));
}

__global__ void stlse_k(const int* __restrict__ rm, const float* __restrict__ rsum,
                        float* __restrict__ stlse) {
    int i = blockIdx.x * 256 + threadIdx.x;
    if (i < Cc) stlse[i] = deord(rm[i]) + __logf(rsum[i]);
}

// phi with obs/init fused; warp-per-row gather + smem transpose, coalesced write
__global__ __launch_bounds__(1024) void phi_k(
    const int* __restrict__ text, const int* __restrict__ w2s,
    const float* __restrict__ trans, const float* __restrict__ tlse,
    const float* __restrict__ L, const float* __restrict__ stlse,
    const float* __restrict__ slog, const float* __restrict__ slse,
    float* __restrict__ phi)
{
    int b = blockIdx.x;
    int n = b / Tm1, t = b % Tm1;
    __shared__ int c0[SPW], c1[SPW];
    __shared__ float ob1[SPW], iob[SPW], tl0[SPW];
    __shared__ float tile[SPW * 33];
    int tid = threadIdx.x;
    if (tid < SPW) {
        int v0 = text[n * Tt + t], v1 = text[n * Tt + t + 1];
        int cc0 = w2s[v0 * SPW + tid], cc1 = w2s[v1 * SPW + tid];
        c0[tid] = cc0; c1[tid] = cc1;
        tl0[tid] = tlse[cc0];
        ob1[tid] = L[v1 * SPW + tid] - stlse[cc1];
        iob[tid] = (t == 0)
            ? (slog[cc0] - slse[0] + L[v0 * SPW + tid] - stlse[cc0]) : 0.f;
    }
    __syncthreads();
    int jw = tid >> 5, kl = tid & 31;
    float val = __ldg(&trans[(size_t)c0[jw] * Cc + c1[kl]]) - tl0[jw] + ob1[kl] + iob[jw];
    tile[jw * 33 + kl] = val;
    __syncthreads();
    int kw = tid >> 5, jl = tid & 31;
    phi[(size_t)(t * Nn + n) * 1024 + kw * SPW + jl] = tile[jl * 33 + kw];
}

// forward (blocks 0..31) / backward (32..63) scans; 1 barrier per step
__global__ __launch_bounds__(1024) void scan_k(
    const float* __restrict__ phi, float* __restrict__ ap, float* __restrict__ bn,
    float* __restrict__ logZ, float* __restrict__ out)
{
    __shared__ float a_s[2][SPW];
    int tid = threadIdx.x, w = tid >> 5, lane = tid & 31;
    bool bwd = blockIdx.x >= Nn;
    int n = bwd ? (int)blockIdx.x - Nn : (int)blockIdx.x;
    if (tid < SPW) a_s[0][tid] = 0.f;
    __syncthreads();
    int cur = 0;
    if (!bwd) {
        float pv = phi[(size_t)n * 1024 + tid];
        for (int t = 0; t < Tm1; t++) {
            float pvn = (t + 1 < Tm1) ? phi[(size_t)((t + 1) * Nn + n) * 1024 + tid] : 0.f;
            if (tid < SPW) ap[(size_t)(t * Nn + n) * SPW + tid] = a_s[cur][tid];
            float x = pv + a_s[cur][lane];
            float m = warp_max(x);
            float s = warp_sum(__expf(x - m));
            if (lane == 0) a_s[cur ^ 1][w] = m + __logf(s);
            __syncthreads();
            cur ^= 1;
            pv = pvn;
        }
        if (w == 0) {
            float x = a_s[cur][lane];
            float m = warp_max(x);
            float s = warp_sum(__expf(x - m));
            float lz = m + __logf(s);
            if (lane == 0) logZ[n] = lz;
            out[2 + n * SPW + lane] = x - lz;
        }
        if (n == 0 && tid == 1023) out[0] = 0.f;
    } else {
        float pv = phi[(size_t)((Tm1 - 1) * Nn + n) * 1024 + lane * SPW + w];
        for (int t = Tm1 - 1; t >= 0; t--) {
            float pvn = (t > 0) ? phi[(size_t)((t - 1) * Nn + n) * 1024 + lane * SPW + w] : 0.f;
            if (tid < SPW) bn[(size_t)(t * Nn + n) * SPW + tid] = a_s[cur][tid];
            float x = pv + a_s[cur][lane];
            float m = warp_max(x);
            float s = warp_sum(__expf(x - m));
            if (lane == 0) a_s[cur ^ 1][w] = m + __logf(s);
            __syncthreads();
            cur ^= 1;
            pv = pvn;
        }
    }
}

// elbo + evidence fused
__global__ __launch_bounds__(1024) void elbo_k(
    const float* __restrict__ phi, const float* __restrict__ ap,
    const float* __restrict__ bn, const float* __restrict__ logZ,
    float* __restrict__ out)
{
    int e = blockIdx.x;
    int n = e % Nn;
    __shared__ float sap[SPW], sbn[SPW], ws[32];
    int tid = threadIdx.x;
    if (tid < SPW) { sap[tid] = ap[(size_t)e * SPW + tid]; sbn[tid] = bn[(size_t)e * SPW + tid]; }
    __syncthreads();
    int k = tid >> 5, j = tid & 31;
    float p = phi[(size_t)e * 1024 + tid];
    float term = __expf(sap[j] + p + sbn[k] - logZ[n]) * p;
    term = warp_sum(term);
    if (j == 0) ws[k] = term;
    __syncthreads();
    if (tid < 32) {
        float v = warp_sum(ws[tid]);
        if (tid == 0) atomicAdd(&out[0], v);
    }
    if (e == 0 && tid >= 64 && tid < 96) {
        int lane2 = tid - 64;
        float lz = logZ[lane2];
        lz = warp_sum(lz);
        if (lane2 == 0) out[1] = lz;
    }
}

// ---------------- launcher ----------------
extern "C" void kernel_launch(void* const* d_in, const int* in_sizes, int n_in,
                              void* d_out, int out_size) {
    const float* start_emb = (const float*)d_in[0];
    const float* sw1  = (const float*)d_in[1];
    const float* sb1  = (const float*)d_in[2];
    const float* sw2  = (const float*)d_in[3];
    const float* sb2  = (const float*)d_in[4];
    const float* s_out_w = (const float*)d_in[5];
    const float* s_out_b = (const float*)d_in[6];
    const float* state_emb = (const float*)d_in[7];
    const float* tw1  = (const float*)d_in[8];
    const float* tb1  = (const float*)d_in[9];
    const float* tw2  = (const float*)d_in[10];
    const float* tb2  = (const float*)d_in[11];
    const float* nsp  = (const float*)d_in[12];
    const float* pre_emb = (const float*)d_in[13];
    const float* ew1  = (const float*)d_in[14];
    const float* eb1  = (const float*)d_in[15];
    const float* ew2  = (const float*)d_in[16];
    const float* eb2  = (const float*)d_in[17];
    const float* e_out_w = (const float*)d_in[18];
    const float* e_out_b = (const float*)d_in[19];
    const int* text = (const int*)d_in[20];
    const int* w2s  = (const int*)d_in[21];
    float* out = (float*)d_out;

    float* S = nullptr; int* RM = nullptr; uint32_t* U = nullptr;
    cudaGetSymbolAddress((void**)&S, g_scr);
    cudaGetSymbolAddress((void**)&RM, g_rowmax);
    cudaGetSymbolAddress((void**)&U, g_u);

    static bool inited = false;
    static cudaStream_t s1;
    static cudaEvent_t evStart, evB2, evEm;
    if (!inited) {
        cudaStreamCreateWithFlags(&s1, cudaStreamNonBlocking);
        cudaEventCreateWithFlags(&evStart, cudaEventDisableTiming);
        cudaEventCreateWithFlags(&evB2, cudaEventDisableTiming);
        cudaEventCreateWithFlags(&evEm, cudaEventDisableTiming);
        inited = true;
    }

    cudaEventRecord(evStart, 0);
    cudaStreamWaitEvent(s1, evStart, 0);

    // ---- s1: ewT transpose + inits (overlaps prep + MLPs) ----
    prep2_k<<<4032, 256, 0, s1>>>(e_out_w, S + OFF_EWT, RM, S + OFF_RSUM,
                                  S + OFF_SLOG, s_out_b);

    // ---- main: presplit + weight splits ----
    Prep P;
    const float* em_[4] = { start_emb, state_emb, pre_emb, nsp };
    for (int j = 0; j < 3; j++) {
        P.psrc[j] = em_[j];
        P.phid[j] = (__half*)(U + HEMB + (size_t)j * 2 * HS);
        P.plod[j] = (__half*)(U + HEMB + (size_t)j * 2 * HS + HS);
    }
    P.psrc[3] = nsp;
    P.phid[3] = (__half*)(U + NSPh);
    P.plod[3] = (__half*)(U + NSPl);
    const float* ws_[6] = { sw1, tw1, ew1, sw2, tw2, ew2 };
    for (int j = 0; j < 6; j++) {
        P.wsrc[j] = ws_[j];
        P.whid[j] = (__half*)(U + HWB + (size_t)j * 2 * HWS);
        P.wlod[j] = (__half*)(U + HWB + (size_t)j * 2 * HWS + HWS);
    }
    prep_k<<<4480, 256>>>(P);

    // ---- MLPs (fp16 3-split, ldmatrix) ----
    const float* b1_[3] = { sb1, tb1, eb1 };
    PH3 m1;
    for (int j = 0; j < 3; j++) {
        PH& q = m1.p[j];
        q.Ah = (const __half*)(U + HEMB + (size_t)j * 2 * HS);
        q.Al = (const __half*)(U + HEMB + (size_t)j * 2 * HS + HS);
        q.Bh = (const __half*)(U + HWB + (size_t)j * 2 * HWS);
        q.Bl = (const __half*)(U + HWB + (size_t)j * 2 * HWS + HWS);
        q.bias = b1_[j]; q.R = nullptr; q.sw = nullptr; q.C = nullptr;
        q.Oh = (__half*)(U + HOUT + (size_t)j * 2 * HS);
        q.Ol = (__half*)(U + HOUT + (size_t)j * 2 * HS + HS);
    }
    gemmp_h<1><<<dim3(Hh / 64, Cc / 128, 3), 256>>>(m1, nullptr, Hh);

    PH3 m2;
    {
        PH& q = m2.p[0];
        q.Ah = (const __half*)(U + HOUT + 0 * HS);
        q.Al = (const __half*)(U + HOUT + 1 * HS);
        q.Bh = (const __half*)(U + HWB + 3 * 2 * HWS);
        q.Bl = (const __half*)(U + HWB + 3 * 2 * HWS + HWS);
        q.bias = sb2; q.R = start_emb; q.sw = s_out_w;
        q.C = S + OFF_RS; q.Oh = nullptr; q.Ol = nullptr;
    }
    {
        PH& q = m2.p[1];
        q.Ah = (const __half*)(U + HOUT + 2 * HS);
        q.Al = (const __half*)(U + HOUT + 3 * HS);
        q.Bh = (const __half*)(U + HWB + 4 * 2 * HWS);
        q.Bl = (const __half*)(U + HWB + 4 * 2 * HWS + HWS);
        q.bias = tb2; q.R = state_emb; q.sw = nullptr;
        q.C = nullptr;
        q.Oh = (__half*)(U + RSTh); q.Ol = (__half*)(U + RSTl);
    }
    {
        PH& q = m2.p[2];
        q.Ah = (const __half*)(U + HOUT + 4 * HS);
        q.Al = (const __half*)(U + HOUT + 5 * HS);
        q.Bh = (const __half*)(U + HWB + 5 * 2 * HWS);
        q.Bl = (const __half*)(U + HWB + 5 * 2 * HWS + HWS);
        q.bias = eb2; q.R = pre_emb; q.sw = nullptr;
        q.C = S + OFF_RP; q.Oh = nullptr; q.Ol = nullptr;
    }
    gemmp_h<2><<<dim3(Hh / 64, Cc / 128, 3), 256>>>(m2, S + OFF_SLOG, Hh);
    cudaEventRecord(evB2, 0);

    // ---- s1: emission chain (concurrent with trans GEMM) ----
    cudaStreamWaitEvent(s1, evB2, 0);
    emlog_k<<<Vv, 256, 0, s1>>>(S + OFF_RP, S + OFF_EWT, e_out_b, w2s, S + OFF_L, RM);
    emsum_k<<<Vv * SPW / 256, 256, 0, s1>>>(w2s, S + OFF_L, RM, S + OFF_RSUM);
    stlse_k<<<16, 256, 0, s1>>>(RM, S + OFF_RSUM, S + OFF_STLSE);
    cudaEventRecord(evEm, s1);

    // ---- main: fp16 trans GEMM (ldmatrix) + merged lse reductions ----
    gemm2_h<<<dim3(Cc / 128, Cc / 128), 256>>>(
        (const __half*)(U + RSTh), (const __half*)(U + RSTl),
        (const __half*)(U + NSPh), (const __half*)(U + NSPl),
        S + OFF_TRANS, (float2*)(S + OFF_PART));
    merge_k<<<513, 256>>>((float2*)(S + OFF_PART), S + OFF_TLSE, S + OFF_SLOG, S + OFF_SLSE);

    // ---- join + tail ----
    cudaStreamWaitEvent(0, evEm, 0);
    phi_k<<<Nn * Tm1, 1024>>>(text, w2s, S + OFF_TRANS, S + OFF_TLSE,
                              S + OFF_L, S + OFF_STLSE, S + OFF_SLOG, S + OFF_SLSE,
                              S + OFF_PHI);
    scan_k<<<2 * Nn, 1024>>>(S + OFF_PHI, S + OFF_AP, S + OFF_BN, S + OFF_LOGZ, out);
    elbo_k<<<Tm1 * Nn, 1024>>>(S + OFF_PHI, S + OFF_AP, S + OFF_BN, S + OFF_LOGZ, out);
}